// round 2
// baseline (speedup 1.0000x reference)
#include <cuda_runtime.h>
#include <math.h>

// ---------------------------------------------------------------------------
// Problem constants (GPT block: B=4, T=2048, C=1024, H=16, D=64)
// ---------------------------------------------------------------------------
#define B_  4
#define T_  2048
#define C_  1024
#define H_  16
#define D_  64
#define M_  (B_ * T_)      // 8192 rows
#define FC_ (4 * C_)       // 4096

// ---------------------------------------------------------------------------
// Scratch buffers (static __device__ — no allocation allowed). 128B aligned
// so float4 access is always legal.
// ---------------------------------------------------------------------------
__device__ __align__(128) float g_ln [M_ * C_];
__device__ __align__(128) float g_q  [M_ * C_];
__device__ __align__(128) float g_k  [M_ * C_];
__device__ __align__(128) float g_v  [M_ * C_];
__device__ __align__(128) float g_att[M_ * C_];
__device__ __align__(128) float g_x1 [M_ * C_];
__device__ __align__(128) float g_fc [M_ * FC_];

// ---------------------------------------------------------------------------
// LayerNorm: one block (256 threads) per row of 1024
// ---------------------------------------------------------------------------
__global__ void ln_kernel(const float* __restrict__ x,
                          const float* __restrict__ gamma,
                          const float* __restrict__ beta,
                          float* __restrict__ y)
{
    int row = blockIdx.x;
    int t   = threadIdx.x;           // 0..255, each handles 4 floats (float4)
    const float4* xr = (const float4*)(x + (size_t)row * C_);
    float4 xv = xr[t];

    float s  = xv.x + xv.y + xv.z + xv.w;
    float ss = fmaf(xv.x, xv.x, fmaf(xv.y, xv.y, fmaf(xv.z, xv.z, xv.w * xv.w)));

    #pragma unroll
    for (int o = 16; o > 0; o >>= 1) {
        s  += __shfl_xor_sync(0xffffffffu, s,  o);
        ss += __shfl_xor_sync(0xffffffffu, ss, o);
    }
    __shared__ float rs[8], rss[8];
    __shared__ float s_mu, s_inv;
    int w = t >> 5, lane = t & 31;
    if (lane == 0) { rs[w] = s; rss[w] = ss; }
    __syncthreads();
    if (t == 0) {
        float ts = 0.f, tss = 0.f;
        #pragma unroll
        for (int i = 0; i < 8; i++) { ts += rs[i]; tss += rss[i]; }
        float mu  = ts * (1.0f / (float)C_);
        float var = tss * (1.0f / (float)C_) - mu * mu;
        s_mu  = mu;
        s_inv = rsqrtf(var + 1e-5f);
    }
    __syncthreads();
    float mu = s_mu, inv = s_inv;

    float4 gv = ((const float4*)gamma)[t];
    float4 bv = ((const float4*)beta)[t];
    float4 ov;
    ov.x = (xv.x - mu) * inv * gv.x + bv.x;
    ov.y = (xv.y - mu) * inv * gv.y + bv.y;
    ov.z = (xv.z - mu) * inv * gv.z + bv.z;
    ov.w = (xv.w - mu) * inv * gv.w + bv.w;
    ((float4*)(y + (size_t)row * C_))[t] = ov;
}

// ---------------------------------------------------------------------------
// GELU (tanh approximation, matching reference)
// ---------------------------------------------------------------------------
__device__ __forceinline__ float gelu_f(float x)
{
    float x3 = x * x * x;
    return 0.5f * x * (1.0f + tanhf(0.7978845608028654f * (x + 0.044715f * x3)));
}

// ---------------------------------------------------------------------------
// SGEMM: C[M,N] = A[M,K] @ B[K,N] (+ bias[N]) (+ epilogue)
//   epi = 0: + bias
//   epi = 1: gelu(+ bias)
//   epi = 2: + bias + resid[M,N]
// BM=BN=128, BK=8, 256 threads, 8x8 per thread. All dims multiples of tile.
// ---------------------------------------------------------------------------
__global__ void sgemm_kernel(const float* __restrict__ A,
                             const float* __restrict__ Bm,
                             const float* __restrict__ bias,
                             const float* __restrict__ resid,
                             float* __restrict__ C,
                             int M, int N, int K, int epi)
{
    __shared__ float As[8][128];
    __shared__ float Bs[8][128];

    int tid = threadIdx.x;               // 0..255
    int bx  = blockIdx.x;                // N tiles
    int by  = blockIdx.y;                // M tiles
    int tx  = tid & 15;                  // 0..15 (N)
    int ty  = tid >> 4;                  // 0..15 (M)

    float acc[8][8];
    #pragma unroll
    for (int i = 0; i < 8; i++)
        #pragma unroll
        for (int j = 0; j < 8; j++) acc[i][j] = 0.f;

    int aRow = tid >> 1;                 // 0..127
    int aCol = (tid & 1) * 4;            // 0 or 4
    int bRow = tid >> 5;                 // 0..7
    int bCol = (tid & 31) * 4;           // 0..124

    const float* Aptr = A + (size_t)(by * 128 + aRow) * K + aCol;
    const float* Bptr = Bm + (size_t)bRow * N + bx * 128 + bCol;

    for (int k0 = 0; k0 < K; k0 += 8) {
        float4 a = *(const float4*)(Aptr + k0);
        As[aCol + 0][aRow] = a.x;
        As[aCol + 1][aRow] = a.y;
        As[aCol + 2][aRow] = a.z;
        As[aCol + 3][aRow] = a.w;
        *(float4*)&Bs[bRow][bCol] = *(const float4*)(Bptr + (size_t)k0 * N);
        __syncthreads();

        #pragma unroll
        for (int k = 0; k < 8; k++) {
            float ar[8], br[8];
            #pragma unroll
            for (int i = 0; i < 8; i++) ar[i] = As[k][ty * 8 + i];
            #pragma unroll
            for (int j = 0; j < 8; j++) br[j] = Bs[k][tx * 8 + j];
            #pragma unroll
            for (int i = 0; i < 8; i++)
                #pragma unroll
                for (int j = 0; j < 8; j++)
                    acc[i][j] = fmaf(ar[i], br[j], acc[i][j]);
        }
        __syncthreads();
    }

    // epilogue
    int col0 = bx * 128 + tx * 8;
    #pragma unroll
    for (int i = 0; i < 8; i++) {
        size_t row = (size_t)(by * 128 + ty * 8 + i);
        float v[8];
        #pragma unroll
        for (int j = 0; j < 8; j++) {
            float t = acc[i][j] + bias[col0 + j];
            if (epi == 1) t = gelu_f(t);
            else if (epi == 2) t += resid[row * N + col0 + j];
            v[j] = t;
        }
        float4* dst = (float4*)(C + row * N + col0);
        dst[0] = make_float4(v[0], v[1], v[2], v[3]);
        dst[1] = make_float4(v[4], v[5], v[6], v[7]);
    }
}

// ---------------------------------------------------------------------------
// Flash attention (fp32, causal). Block: 64 query rows x full head (D=64).
// 256 threads: row = tid>>2 (0..63), q4 = tid&3 owns 16 cols/dims.
// Tiles of 64 keys, online softmax. smem stride 65 avoids bank conflicts;
// all smem stores are SCALAR (stride 65 rows are not 16B aligned).
// ---------------------------------------------------------------------------
#define ATTN_SMEM (4 * 64 * 65 * 4)   // Qs,Ks,Vs,Ss each 64x65 floats

__global__ void attn_kernel(const float* __restrict__ Q,
                            const float* __restrict__ K,
                            const float* __restrict__ V,
                            float* __restrict__ O)
{
    extern __shared__ float sm[];
    float* Qs = sm;
    float* Ks = sm + 64 * 65;
    float* Vs = sm + 2 * 64 * 65;
    float* Ss = sm + 3 * 64 * 65;

    int qt = blockIdx.x;           // query tile (0..31)
    int h  = blockIdx.y;
    int b  = blockIdx.z;
    int tid = threadIdx.x;
    int row = tid >> 2;            // 0..63
    int q4  = tid & 3;             // 0..3

    // Load Q tile (64 rows x 64 dims): float4 global load, scalar smem store
    const size_t base_q = ((size_t)(b * T_ + qt * 64)) * C_ + h * D_;
    #pragma unroll
    for (int i = 0; i < 4; i++) {
        int lc = q4 * 16 + i * 4;
        float4 qv = *(const float4*)&Q[base_q + (size_t)row * C_ + lc];
        Qs[row * 65 + lc + 0] = qv.x;
        Qs[row * 65 + lc + 1] = qv.y;
        Qs[row * 65 + lc + 2] = qv.z;
        Qs[row * 65 + lc + 3] = qv.w;
    }

    float m = -1e30f, l = 0.f;
    float acc[16];
    #pragma unroll
    for (int d = 0; d < 16; d++) acc[d] = 0.f;

    const int qrow = qt * 64 + row;
    const int nkt = qt + 1;

    for (int kt = 0; kt < nkt; kt++) {
        __syncthreads();  // prior reads of Ks/Vs/Ss complete (also covers Qs on iter 0)
        const size_t base_k = ((size_t)(b * T_ + kt * 64)) * C_ + h * D_;
        #pragma unroll
        for (int i = 0; i < 4; i++) {
            int lc = q4 * 16 + i * 4;
            float4 kv = *(const float4*)&K[base_k + (size_t)row * C_ + lc];
            float4 vv = *(const float4*)&V[base_k + (size_t)row * C_ + lc];
            Ks[row * 65 + lc + 0] = kv.x;
            Ks[row * 65 + lc + 1] = kv.y;
            Ks[row * 65 + lc + 2] = kv.z;
            Ks[row * 65 + lc + 3] = kv.w;
            Vs[row * 65 + lc + 0] = vv.x;
            Vs[row * 65 + lc + 1] = vv.y;
            Vs[row * 65 + lc + 2] = vv.z;
            Vs[row * 65 + lc + 3] = vv.w;
        }
        __syncthreads();

        // S[row][q4*16 .. +15] = Q[row,:] . K[c,:]
        float s[16];
        #pragma unroll
        for (int c = 0; c < 16; c++) s[c] = 0.f;
        #pragma unroll 16
        for (int k = 0; k < 64; k++) {
            float qv = Qs[row * 65 + k];
            #pragma unroll
            for (int c = 0; c < 16; c++)
                s[c] = fmaf(qv, Ks[(q4 * 16 + c) * 65 + k], s[c]);
        }

        // scale + causal mask + tile max
        float lm = -1e30f;
        #pragma unroll
        for (int c = 0; c < 16; c++) {
            int kcol = kt * 64 + q4 * 16 + c;
            s[c] *= 0.125f;                    // 1/sqrt(64)
            if (kcol > qrow) s[c] = -1e30f;
            lm = fmaxf(lm, s[c]);
        }
        lm = fmaxf(lm, __shfl_xor_sync(0xffffffffu, lm, 1));
        lm = fmaxf(lm, __shfl_xor_sync(0xffffffffu, lm, 2));

        float mn   = fmaxf(m, lm);
        float corr = __expf(m - mn);
        float ls = 0.f;
        #pragma unroll
        for (int c = 0; c < 16; c++) {
            s[c] = __expf(s[c] - mn);
            ls += s[c];
        }
        ls += __shfl_xor_sync(0xffffffffu, ls, 1);
        ls += __shfl_xor_sync(0xffffffffu, ls, 2);
        l = l * corr + ls;
        m = mn;
        #pragma unroll
        for (int d = 0; d < 16; d++) acc[d] *= corr;

        // share P across the 4 threads of each row
        #pragma unroll
        for (int c = 0; c < 16; c++) Ss[row * 65 + q4 * 16 + c] = s[c];
        __syncwarp();

        // acc[d] += sum_k P[row][k] * V[k][d]   (d = q4*16 .. +15)
        #pragma unroll 16
        for (int k = 0; k < 64; k++) {
            float pv = Ss[row * 65 + k];
            #pragma unroll
            for (int d = 0; d < 16; d++)
                acc[d] = fmaf(pv, Vs[k * 65 + q4 * 16 + d], acc[d]);
        }
    }

    float invl = 1.0f / l;
    size_t obase = ((size_t)(b * T_ + qrow)) * C_ + h * D_ + q4 * 16;
    #pragma unroll
    for (int i = 0; i < 4; i++) {
        float4 ov = make_float4(acc[i * 4 + 0] * invl, acc[i * 4 + 1] * invl,
                                acc[i * 4 + 2] * invl, acc[i * 4 + 3] * invl);
        *(float4*)&O[obase + i * 4] = ov;
    }
}

// ---------------------------------------------------------------------------
// Launch
// ---------------------------------------------------------------------------
extern "C" void kernel_launch(void* const* d_in, const int* in_sizes, int n_in,
                              void* d_out, int out_size)
{
    const float* x      = (const float*)d_in[0];
    const float* Wq     = (const float*)d_in[1];
    const float* bq     = (const float*)d_in[2];
    const float* Wk     = (const float*)d_in[3];
    const float* bk     = (const float*)d_in[4];
    const float* Wv     = (const float*)d_in[5];
    const float* bv     = (const float*)d_in[6];
    const float* Wo     = (const float*)d_in[7];
    const float* bo     = (const float*)d_in[8];
    const float* ln1_g  = (const float*)d_in[9];
    const float* ln1_b  = (const float*)d_in[10];
    const float* ln2_g  = (const float*)d_in[11];
    const float* ln2_b  = (const float*)d_in[12];
    const float* W_fc   = (const float*)d_in[13];
    const float* b_fc   = (const float*)d_in[14];
    const float* W_proj = (const float*)d_in[15];
    const float* b_proj = (const float*)d_in[16];
    float* out = (float*)d_out;

    float *ln, *q, *k, *v, *att, *x1, *fc;
    cudaGetSymbolAddress((void**)&ln,  g_ln);
    cudaGetSymbolAddress((void**)&q,   g_q);
    cudaGetSymbolAddress((void**)&k,   g_k);
    cudaGetSymbolAddress((void**)&v,   g_v);
    cudaGetSymbolAddress((void**)&att, g_att);
    cudaGetSymbolAddress((void**)&x1,  g_x1);
    cudaGetSymbolAddress((void**)&fc,  g_fc);

    cudaFuncSetAttribute(attn_kernel,
                         cudaFuncAttributeMaxDynamicSharedMemorySize, ATTN_SMEM);

    dim3 gC(C_ / 128, M_ / 128);     // (8, 64)
    dim3 gF(FC_ / 128, M_ / 128);    // (32, 64)

    // 1) ln1 = LN(x)
    ln_kernel<<<M_, 256>>>(x, ln1_g, ln1_b, ln);
    // 2) q, k, v
    sgemm_kernel<<<gC, 256>>>(ln, Wq, bq, nullptr, q, M_, C_, C_, 0);
    sgemm_kernel<<<gC, 256>>>(ln, Wk, bk, nullptr, k, M_, C_, C_, 0);
    sgemm_kernel<<<gC, 256>>>(ln, Wv, bv, nullptr, v, M_, C_, C_, 0);
    // 3) causal attention -> (B,T,C) layout
    attn_kernel<<<dim3(T_ / 64, H_, B_), 256, ATTN_SMEM>>>(q, k, v, att);
    // 4) x1 = x + att @ Wo + bo
    sgemm_kernel<<<gC, 256>>>(att, Wo, bo, x, x1, M_, C_, C_, 2);
    // 5) ln2 = LN(x1)
    ln_kernel<<<M_, 256>>>(x1, ln2_g, ln2_b, ln);
    // 6) fc = gelu(ln2 @ W_fc + b_fc)
    sgemm_kernel<<<gF, 256>>>(ln, W_fc, b_fc, nullptr, fc, M_, FC_, C_, 1);
    // 7) out = x1 + fc @ W_proj + b_proj
    sgemm_kernel<<<gC, 256>>>(fc, W_proj, b_proj, x1, out, M_, C_, FC_, 2);
}

// round 3
// speedup vs baseline: 1.7328x; 1.7328x over previous
#include <cuda_runtime.h>
#include <math.h>

// ---------------------------------------------------------------------------
// GPT block: B=4, T=2048, C=1024, H=16, D=64
// ---------------------------------------------------------------------------
#define B_  4
#define T_  2048
#define C_  1024
#define H_  16
#define D_  64
#define M_  (B_ * T_)      // 8192
#define FC_ (4 * C_)       // 4096

// ---------------------------------------------------------------------------
// Scratch (static __device__, 128B aligned for float4)
// ---------------------------------------------------------------------------
__device__ __align__(128) float g_ln [M_ * C_];
__device__ __align__(128) float g_q  [M_ * C_];
__device__ __align__(128) float g_k  [M_ * C_];
__device__ __align__(128) float g_v  [M_ * C_];
__device__ __align__(128) float g_att[M_ * C_];
__device__ __align__(128) float g_x1 [M_ * C_];
__device__ __align__(128) float g_fc [M_ * FC_];

// ---------------------------------------------------------------------------
// LayerNorm: one block (256 threads) per row of 1024
// ---------------------------------------------------------------------------
__global__ void ln_kernel(const float* __restrict__ x,
                          const float* __restrict__ gamma,
                          const float* __restrict__ beta,
                          float* __restrict__ y)
{
    int row = blockIdx.x;
    int t   = threadIdx.x;
    const float4* xr = (const float4*)(x + (size_t)row * C_);
    float4 xv = xr[t];

    float s  = xv.x + xv.y + xv.z + xv.w;
    float ss = fmaf(xv.x, xv.x, fmaf(xv.y, xv.y, fmaf(xv.z, xv.z, xv.w * xv.w)));

    #pragma unroll
    for (int o = 16; o > 0; o >>= 1) {
        s  += __shfl_xor_sync(0xffffffffu, s,  o);
        ss += __shfl_xor_sync(0xffffffffu, ss, o);
    }
    __shared__ float rs[8], rss[8];
    __shared__ float s_mu, s_inv;
    int w = t >> 5, lane = t & 31;
    if (lane == 0) { rs[w] = s; rss[w] = ss; }
    __syncthreads();
    if (t == 0) {
        float ts = 0.f, tss = 0.f;
        #pragma unroll
        for (int i = 0; i < 8; i++) { ts += rs[i]; tss += rss[i]; }
        float mu  = ts * (1.0f / (float)C_);
        float var = tss * (1.0f / (float)C_) - mu * mu;
        s_mu  = mu;
        s_inv = rsqrtf(var + 1e-5f);
    }
    __syncthreads();
    float mu = s_mu, inv = s_inv;

    float4 gv = ((const float4*)gamma)[t];
    float4 bv = ((const float4*)beta)[t];
    float4 ov;
    ov.x = (xv.x - mu) * inv * gv.x + bv.x;
    ov.y = (xv.y - mu) * inv * gv.y + bv.y;
    ov.z = (xv.z - mu) * inv * gv.z + bv.z;
    ov.w = (xv.w - mu) * inv * gv.w + bv.w;
    ((float4*)(y + (size_t)row * C_))[t] = ov;
}

__device__ __forceinline__ float gelu_f(float x)
{
    float x3 = x * x * x;
    return 0.5f * x * (1.0f + tanhf(0.7978845608028654f * (x + 0.044715f * x3)));
}

// ---------------------------------------------------------------------------
// SGEMM: C[M,N] = A[M,K] @ B[K,N] (+bias) (+gelu | +resid)
// BM=BN=128, BK=16, 256 threads, 8x8/thread, double-buffered smem,
// register-prefetch pipeline. All dims multiples of tile sizes.
// ---------------------------------------------------------------------------
__global__ void __launch_bounds__(256, 2)
sgemm_kernel(const float* __restrict__ A,
             const float* __restrict__ Bm,
             const float* __restrict__ bias,
             const float* __restrict__ resid,
             float* __restrict__ C,
             int M, int N, int K, int epi)
{
    __shared__ float As[2][16][132];   // transposed: As[k][m], padded stride
    __shared__ float Bs[2][16][128];   // Bs[k][n]

    const int tid = threadIdx.x;
    const int bx  = blockIdx.x;
    const int by  = blockIdx.y;
    const int tx  = tid & 15;
    const int ty  = tid >> 4;

    // loader mappings
    const int aRow = tid >> 2;           // 0..63 (also +64)
    const int aCol = (tid & 3) * 4;      // 0,4,8,12
    const int bRow = tid >> 5;           // 0..7 (also +8)
    const int bCol = (tid & 31) * 4;     // 0..124

    const float* Aptr = A + (size_t)(by * 128 + aRow) * K + aCol;
    const float* Bptr = Bm + (size_t)bRow * N + bx * 128 + bCol;
    const size_t aRowStride = (size_t)64 * K;
    const size_t bRowStride = (size_t)8 * N;

    float acc[8][8];
    #pragma unroll
    for (int i = 0; i < 8; i++)
        #pragma unroll
        for (int j = 0; j < 8; j++) acc[i][j] = 0.f;

    // preload chunk 0
    float4 a0 = *(const float4*)(Aptr);
    float4 a1 = *(const float4*)(Aptr + aRowStride);
    float4 b0 = *(const float4*)(Bptr);
    float4 b1 = *(const float4*)(Bptr + bRowStride);

    As[0][aCol + 0][aRow]      = a0.x;
    As[0][aCol + 1][aRow]      = a0.y;
    As[0][aCol + 2][aRow]      = a0.z;
    As[0][aCol + 3][aRow]      = a0.w;
    As[0][aCol + 0][aRow + 64] = a1.x;
    As[0][aCol + 1][aRow + 64] = a1.y;
    As[0][aCol + 2][aRow + 64] = a1.z;
    As[0][aCol + 3][aRow + 64] = a1.w;
    *(float4*)&Bs[0][bRow][bCol]     = b0;
    *(float4*)&Bs[0][bRow + 8][bCol] = b1;
    __syncthreads();

    int buf = 0;
    for (int k0 = 16; k0 <= K; k0 += 16) {
        // prefetch next chunk (if any)
        if (k0 < K) {
            a0 = *(const float4*)(Aptr + k0);
            a1 = *(const float4*)(Aptr + k0 + aRowStride);
            b0 = *(const float4*)(Bptr + (size_t)k0 * N);
            b1 = *(const float4*)(Bptr + (size_t)k0 * N + bRowStride);
        }

        // compute on current buffer
        #pragma unroll
        for (int k = 0; k < 16; k++) {
            float4 arl = *(const float4*)&As[buf][k][ty * 8];
            float4 arh = *(const float4*)&As[buf][k][ty * 8 + 4];
            float4 brl = *(const float4*)&Bs[buf][k][tx * 8];
            float4 brh = *(const float4*)&Bs[buf][k][tx * 8 + 4];
            float ar[8] = {arl.x, arl.y, arl.z, arl.w, arh.x, arh.y, arh.z, arh.w};
            float br[8] = {brl.x, brl.y, brl.z, brl.w, brh.x, brh.y, brh.z, brh.w};
            #pragma unroll
            for (int i = 0; i < 8; i++)
                #pragma unroll
                for (int j = 0; j < 8; j++)
                    acc[i][j] = fmaf(ar[i], br[j], acc[i][j]);
        }

        if (k0 < K) {
            int nb = buf ^ 1;
            As[nb][aCol + 0][aRow]      = a0.x;
            As[nb][aCol + 1][aRow]      = a0.y;
            As[nb][aCol + 2][aRow]      = a0.z;
            As[nb][aCol + 3][aRow]      = a0.w;
            As[nb][aCol + 0][aRow + 64] = a1.x;
            As[nb][aCol + 1][aRow + 64] = a1.y;
            As[nb][aCol + 2][aRow + 64] = a1.z;
            As[nb][aCol + 3][aRow + 64] = a1.w;
            *(float4*)&Bs[nb][bRow][bCol]     = b0;
            *(float4*)&Bs[nb][bRow + 8][bCol] = b1;
            __syncthreads();
            buf = nb;
        }
    }

    // epilogue
    const int col0 = bx * 128 + tx * 8;
    #pragma unroll
    for (int i = 0; i < 8; i++) {
        size_t row = (size_t)(by * 128 + ty * 8 + i);
        float v[8];
        #pragma unroll
        for (int j = 0; j < 8; j++) {
            float t = acc[i][j] + bias[col0 + j];
            if (epi == 1) t = gelu_f(t);
            else if (epi == 2) t += resid[row * N + col0 + j];
            v[j] = t;
        }
        float4* dst = (float4*)(C + row * N + col0);
        dst[0] = make_float4(v[0], v[1], v[2], v[3]);
        dst[1] = make_float4(v[4], v[5], v[6], v[7]);
    }
}

// ---------------------------------------------------------------------------
// Flash attention (fp32, causal), register-tiled.
// Block = 64 queries x D=64, 256 threads, each thread 4x4 fragment.
// Layouts: Qs[d][q], Ks[d][kv], Vs[kv][d], Ps[kv][q], stride 68 (16B-aligned,
// conflict-light). Inner loops: 2x LDS.128 per 16 FMA.
// ---------------------------------------------------------------------------
#define AS_ 68
#define ATTN_SMEM (4 * 64 * AS_ * 4)

__global__ void __launch_bounds__(256)
attn_kernel(const float* __restrict__ Q,
            const float* __restrict__ K,
            const float* __restrict__ V,
            float* __restrict__ O)
{
    extern __shared__ float sm[];
    float* Qs = sm;                    // [d][q]
    float* Ks = sm + 64 * AS_;         // [d][kv]
    float* Vs = sm + 2 * 64 * AS_;     // [kv][d]
    float* Ps = sm + 3 * 64 * AS_;     // [kv][q]

    const int qt  = blockIdx.x;
    const int h   = blockIdx.y;
    const int b   = blockIdx.z;
    const int tid = threadIdx.x;

    const int lrow = tid >> 2;         // loader: 0..63
    const int lq4  = tid & 3;
    const int ty   = tid >> 4;         // compute: rows ty*4..+3
    const int tx   = tid & 15;         // compute: cols tx*4..+3

    // load Q tile, transposed into Qs[d][q]
    const size_t base_q = ((size_t)(b * T_ + qt * 64)) * C_ + h * D_;
    #pragma unroll
    for (int i = 0; i < 4; i++) {
        int col = lq4 * 16 + i * 4;
        float4 qv = *(const float4*)&Q[base_q + (size_t)lrow * C_ + col];
        Qs[(col + 0) * AS_ + lrow] = qv.x;
        Qs[(col + 1) * AS_ + lrow] = qv.y;
        Qs[(col + 2) * AS_ + lrow] = qv.z;
        Qs[(col + 3) * AS_ + lrow] = qv.w;
    }

    float m[4], l[4], acc[4][4];
    #pragma unroll
    for (int i = 0; i < 4; i++) {
        m[i] = -1e30f; l[i] = 0.f;
        #pragma unroll
        for (int j = 0; j < 4; j++) acc[i][j] = 0.f;
    }

    for (int kt = 0; kt <= qt; kt++) {
        __syncthreads();   // previous-iter readers of Ks/Vs/Ps done (iter0: Qs stores)
        const size_t base_k = ((size_t)(b * T_ + kt * 64)) * C_ + h * D_;
        #pragma unroll
        for (int i = 0; i < 4; i++) {
            int col = lq4 * 16 + i * 4;
            float4 kv = *(const float4*)&K[base_k + (size_t)lrow * C_ + col];
            // K transposed -> Ks[d][kv]
            Ks[(col + 0) * AS_ + lrow] = kv.x;
            Ks[(col + 1) * AS_ + lrow] = kv.y;
            Ks[(col + 2) * AS_ + lrow] = kv.z;
            Ks[(col + 3) * AS_ + lrow] = kv.w;
            // V natural -> Vs[kv][d]
            float4 vv = *(const float4*)&V[base_k + (size_t)lrow * C_ + col];
            *(float4*)&Vs[lrow * AS_ + col] = vv;
        }
        __syncthreads();

        // S = Q . K^T  (4x4 fragment per thread)
        float s[4][4];
        #pragma unroll
        for (int i = 0; i < 4; i++)
            #pragma unroll
            for (int j = 0; j < 4; j++) s[i][j] = 0.f;
        #pragma unroll 8
        for (int d = 0; d < 64; d++) {
            float4 qf = *(const float4*)&Qs[d * AS_ + ty * 4];
            float4 kf = *(const float4*)&Ks[d * AS_ + tx * 4];
            float qa[4] = {qf.x, qf.y, qf.z, qf.w};
            float ka[4] = {kf.x, kf.y, kf.z, kf.w};
            #pragma unroll
            for (int i = 0; i < 4; i++)
                #pragma unroll
                for (int j = 0; j < 4; j++)
                    s[i][j] = fmaf(qa[i], ka[j], s[i][j]);
        }

        // scale + causal mask + online softmax
        float corr[4];
        #pragma unroll
        for (int i = 0; i < 4; i++) {
            int qrow = qt * 64 + ty * 4 + i;
            float lm = -1e30f;
            #pragma unroll
            for (int j = 0; j < 4; j++) {
                int kcol = kt * 64 + tx * 4 + j;
                float t = s[i][j] * 0.125f;
                if (kcol > qrow) t = -1e30f;
                s[i][j] = t;
                lm = fmaxf(lm, t);
            }
            lm = fmaxf(lm, __shfl_xor_sync(0xffffffffu, lm, 1));
            lm = fmaxf(lm, __shfl_xor_sync(0xffffffffu, lm, 2));
            lm = fmaxf(lm, __shfl_xor_sync(0xffffffffu, lm, 4));
            lm = fmaxf(lm, __shfl_xor_sync(0xffffffffu, lm, 8));

            float mn = fmaxf(m[i], lm);
            corr[i]  = __expf(m[i] - mn);
            m[i]     = mn;

            float ls = 0.f;
            #pragma unroll
            for (int j = 0; j < 4; j++) {
                s[i][j] = __expf(s[i][j] - mn);
                ls += s[i][j];
            }
            ls += __shfl_xor_sync(0xffffffffu, ls, 1);
            ls += __shfl_xor_sync(0xffffffffu, ls, 2);
            ls += __shfl_xor_sync(0xffffffffu, ls, 4);
            ls += __shfl_xor_sync(0xffffffffu, ls, 8);
            l[i] = l[i] * corr[i] + ls;

            #pragma unroll
            for (int j = 0; j < 4; j++) acc[i][j] *= corr[i];
        }

        // write P transposed: Ps[kv][q]
        #pragma unroll
        for (int i = 0; i < 4; i++)
            #pragma unroll
            for (int j = 0; j < 4; j++)
                Ps[(tx * 4 + j) * AS_ + ty * 4 + i] = s[i][j];
        __syncthreads();

        // O += P . V   (sum over kv)
        #pragma unroll 8
        for (int k = 0; k < 64; k++) {
            float4 pf = *(const float4*)&Ps[k * AS_ + ty * 4];
            float4 vf = *(const float4*)&Vs[k * AS_ + tx * 4];
            float pa[4] = {pf.x, pf.y, pf.z, pf.w};
            float va[4] = {vf.x, vf.y, vf.z, vf.w};
            #pragma unroll
            for (int i = 0; i < 4; i++)
                #pragma unroll
                for (int j = 0; j < 4; j++)
                    acc[i][j] = fmaf(pa[i], va[j], acc[i][j]);
        }
    }

    // write O
    #pragma unroll
    for (int i = 0; i < 4; i++) {
        float invl = 1.0f / l[i];
        size_t orow = (size_t)(b * T_ + qt * 64 + ty * 4 + i);
        float4 ov = make_float4(acc[i][0] * invl, acc[i][1] * invl,
                                acc[i][2] * invl, acc[i][3] * invl);
        *(float4*)&O[orow * C_ + h * D_ + tx * 4] = ov;
    }
}

// ---------------------------------------------------------------------------
// Launch
// ---------------------------------------------------------------------------
extern "C" void kernel_launch(void* const* d_in, const int* in_sizes, int n_in,
                              void* d_out, int out_size)
{
    const float* x      = (const float*)d_in[0];
    const float* Wq     = (const float*)d_in[1];
    const float* bq     = (const float*)d_in[2];
    const float* Wk     = (const float*)d_in[3];
    const float* bk     = (const float*)d_in[4];
    const float* Wv     = (const float*)d_in[5];
    const float* bv     = (const float*)d_in[6];
    const float* Wo     = (const float*)d_in[7];
    const float* bo     = (const float*)d_in[8];
    const float* ln1_g  = (const float*)d_in[9];
    const float* ln1_b  = (const float*)d_in[10];
    const float* ln2_g  = (const float*)d_in[11];
    const float* ln2_b  = (const float*)d_in[12];
    const float* W_fc   = (const float*)d_in[13];
    const float* b_fc   = (const float*)d_in[14];
    const float* W_proj = (const float*)d_in[15];
    const float* b_proj = (const float*)d_in[16];
    float* out = (float*)d_out;

    float *ln, *q, *k, *v, *att, *x1, *fc;
    cudaGetSymbolAddress((void**)&ln,  g_ln);
    cudaGetSymbolAddress((void**)&q,   g_q);
    cudaGetSymbolAddress((void**)&k,   g_k);
    cudaGetSymbolAddress((void**)&v,   g_v);
    cudaGetSymbolAddress((void**)&att, g_att);
    cudaGetSymbolAddress((void**)&x1,  g_x1);
    cudaGetSymbolAddress((void**)&fc,  g_fc);

    cudaFuncSetAttribute(attn_kernel,
                         cudaFuncAttributeMaxDynamicSharedMemorySize, ATTN_SMEM);

    dim3 gC(C_ / 128, M_ / 128);     // (8, 64)
    dim3 gF(FC_ / 128, M_ / 128);    // (32, 64)

    ln_kernel<<<M_, 256>>>(x, ln1_g, ln1_b, ln);
    sgemm_kernel<<<gC, 256>>>(ln, Wq, bq, nullptr, q, M_, C_, C_, 0);
    sgemm_kernel<<<gC, 256>>>(ln, Wk, bk, nullptr, k, M_, C_, C_, 0);
    sgemm_kernel<<<gC, 256>>>(ln, Wv, bv, nullptr, v, M_, C_, C_, 0);
    attn_kernel<<<dim3(T_ / 64, H_, B_), 256, ATTN_SMEM>>>(q, k, v, att);
    sgemm_kernel<<<gC, 256>>>(att, Wo, bo, x, x1, M_, C_, C_, 2);
    ln_kernel<<<M_, 256>>>(x1, ln2_g, ln2_b, ln);
    sgemm_kernel<<<gF, 256>>>(ln, W_fc, b_fc, nullptr, fc, M_, FC_, C_, 1);
    sgemm_kernel<<<gC, 256>>>(fc, W_proj, b_proj, x1, out, M_, C_, FC_, 2);
}

// round 5
// speedup vs baseline: 2.9630x; 1.7099x over previous
#include <cuda_runtime.h>
#include <cuda_bf16.h>
#include <math.h>
#include <stdint.h>

// ---------------------------------------------------------------------------
// GPT block: B=4, T=2048, C=1024, H=16, D=64
// ---------------------------------------------------------------------------
#define B_  4
#define T_  2048
#define C_  1024
#define H_  16
#define D_  64
#define M_  (B_ * T_)      // 8192
#define FC_ (4 * C_)       // 4096

// ---------------------------------------------------------------------------
// Helpers
// ---------------------------------------------------------------------------
__device__ __forceinline__ uint32_t smem_u32(const void* p) {
    uint32_t a;
    asm("{ .reg .u64 t; cvta.to.shared.u64 t, %1; cvt.u32.u64 %0, t; }"
        : "=r"(a) : "l"(p));
    return a;
}

__device__ __forceinline__ void split_bf16(float v, __nv_bfloat16& h, __nv_bfloat16& l)
{
    h = __float2bfloat16(v);
    l = __float2bfloat16(v - __bfloat162float(h));
}

__device__ __forceinline__ float gelu_f(float x)
{
    float x3 = x * x * x;
    return 0.5f * x * (1.0f + tanhf(0.7978845608028654f * (x + 0.044715f * x3)));
}

// cp.async 16B
__device__ __forceinline__ void cpa16(uint32_t s, const void* g) {
    asm volatile("cp.async.ca.shared.global [%0], [%1], 16;" :: "r"(s), "l"(g));
}
#define CPA_COMMIT() asm volatile("cp.async.commit_group;" ::: "memory")
#define CPA_WAIT1()  asm volatile("cp.async.wait_group 1;" ::: "memory")
#define CPA_WAIT0()  asm volatile("cp.async.wait_group 0;" ::: "memory")

// ldmatrix x4 (non-transposed)
__device__ __forceinline__ void ldm4(uint32_t* r, uint32_t addr) {
    asm volatile("ldmatrix.sync.aligned.m8n8.x4.shared.b16 {%0,%1,%2,%3}, [%4];"
        : "=r"(r[0]), "=r"(r[1]), "=r"(r[2]), "=r"(r[3]) : "r"(addr));
}

// mma m16n8k16 row.col f32.bf16.bf16.f32
__device__ __forceinline__ void mma16816(float* d, const uint32_t* a, const uint32_t* b) {
    asm volatile("mma.sync.aligned.m16n8k16.row.col.f32.bf16.bf16.f32 "
        "{%0,%1,%2,%3}, {%4,%5,%6,%7}, {%8,%9}, {%0,%1,%2,%3};"
        : "+f"(d[0]), "+f"(d[1]), "+f"(d[2]), "+f"(d[3])
        : "r"(a[0]), "r"(a[1]), "r"(a[2]), "r"(a[3]), "r"(b[0]), "r"(b[1]));
}

// ---------------------------------------------------------------------------
// Scratch (static __device__)
// ---------------------------------------------------------------------------
__device__ __align__(128) __nv_bfloat16 g_lnh [M_ * C_],  g_lnl [M_ * C_];
__device__ __align__(128) __nv_bfloat16 g_atth[M_ * C_],  g_attl[M_ * C_];
__device__ __align__(128) __nv_bfloat16 g_fch [M_ * FC_], g_fcl [M_ * FC_];
__device__ __align__(128) __nv_bfloat16 g_wqh [C_ * C_],  g_wql [C_ * C_];
__device__ __align__(128) __nv_bfloat16 g_wkh [C_ * C_],  g_wkl [C_ * C_];
__device__ __align__(128) __nv_bfloat16 g_wvh [C_ * C_],  g_wvl [C_ * C_];
__device__ __align__(128) __nv_bfloat16 g_woh [C_ * C_],  g_wol [C_ * C_];
__device__ __align__(128) __nv_bfloat16 g_wfh [FC_ * C_], g_wfl [FC_ * C_];   // [N=4C][K=C]
__device__ __align__(128) __nv_bfloat16 g_wph [C_ * FC_], g_wpl [C_ * FC_];   // [N=C][K=4C]
__device__ __align__(128) float g_q [M_ * C_];
__device__ __align__(128) float g_k [M_ * C_];
__device__ __align__(128) float g_v [M_ * C_];
__device__ __align__(128) float g_x1[M_ * C_];

// ---------------------------------------------------------------------------
// Weight transpose + bf16 split: W[K][N] -> Th[N][K], Tl[N][K]
// ---------------------------------------------------------------------------
__global__ void wsplitT_kernel(const float* __restrict__ W,
                               __nv_bfloat16* __restrict__ Th,
                               __nv_bfloat16* __restrict__ Tl,
                               int K, int N)
{
    __shared__ float ts[32][33];
    int tx = threadIdx.x & 31, ty = threadIdx.x >> 5;   // 32 x 8
    int bx = blockIdx.x, by = blockIdx.y;               // N tile, K tile
    #pragma unroll
    for (int i = 0; i < 4; i++) {
        int k = by * 32 + ty + i * 8;
        ts[ty + i * 8][tx] = W[(size_t)k * N + bx * 32 + tx];
    }
    __syncthreads();
    #pragma unroll
    for (int i = 0; i < 4; i++) {
        int n = bx * 32 + ty + i * 8;
        int k = by * 32 + tx;
        float v = ts[tx][ty + i * 8];
        __nv_bfloat16 h, l; split_bf16(v, h, l);
        Th[(size_t)n * K + k] = h;
        Tl[(size_t)n * K + k] = l;
    }
}

// ---------------------------------------------------------------------------
// LayerNorm -> bf16 hi/lo
// ---------------------------------------------------------------------------
__global__ void ln_kernel(const float* __restrict__ x,
                          const float* __restrict__ gamma,
                          const float* __restrict__ beta,
                          __nv_bfloat16* __restrict__ yh,
                          __nv_bfloat16* __restrict__ yl)
{
    int row = blockIdx.x;
    int t   = threadIdx.x;
    const float4* xr = (const float4*)(x + (size_t)row * C_);
    float4 xv = xr[t];

    float s  = xv.x + xv.y + xv.z + xv.w;
    float ss = fmaf(xv.x, xv.x, fmaf(xv.y, xv.y, fmaf(xv.z, xv.z, xv.w * xv.w)));
    #pragma unroll
    for (int o = 16; o > 0; o >>= 1) {
        s  += __shfl_xor_sync(0xffffffffu, s,  o);
        ss += __shfl_xor_sync(0xffffffffu, ss, o);
    }
    __shared__ float rs[8], rss[8];
    __shared__ float s_mu, s_inv;
    int w = t >> 5, lane = t & 31;
    if (lane == 0) { rs[w] = s; rss[w] = ss; }
    __syncthreads();
    if (t == 0) {
        float ts = 0.f, tss = 0.f;
        #pragma unroll
        for (int i = 0; i < 8; i++) { ts += rs[i]; tss += rss[i]; }
        float mu  = ts * (1.0f / (float)C_);
        float var = tss * (1.0f / (float)C_) - mu * mu;
        s_mu = mu;  s_inv = rsqrtf(var + 1e-5f);
    }
    __syncthreads();
    float mu = s_mu, inv = s_inv;

    float4 gv = ((const float4*)gamma)[t];
    float4 bv = ((const float4*)beta)[t];
    float o[4];
    o[0] = (xv.x - mu) * inv * gv.x + bv.x;
    o[1] = (xv.y - mu) * inv * gv.y + bv.y;
    o[2] = (xv.z - mu) * inv * gv.z + bv.z;
    o[3] = (xv.w - mu) * inv * gv.w + bv.w;

    union { __nv_bfloat16 b[4]; uint2 u; } ph, pl;
    #pragma unroll
    for (int i = 0; i < 4; i++) split_bf16(o[i], ph.b[i], pl.b[i]);
    ((uint2*)(yh + (size_t)row * C_))[t] = ph.u;
    ((uint2*)(yl + (size_t)row * C_))[t] = pl.u;
}

// ---------------------------------------------------------------------------
// Tensor-core GEMM via mma.sync (split-bf16 x3, fp32 accum)
// C[M,N] = (Ah+Al)[M,K] @ (Bh+Bl)[N,K]^T   (B stored N-major, K contiguous)
// CTA tile 128x128, BK=32, 8 warps (4M x 2N), warp tile 32x64.
// smem rows padded to 40 bf16 (80B) -> ldmatrix conflict-free.
// cp.async double-buffered pipeline.
//   epi 0: out fp32 = acc + bias
//   epi 1: outH/outL bf16 = split(gelu(acc + bias))
//   epi 2: out fp32 = acc + bias + resid
// ---------------------------------------------------------------------------
#define TROW 40                       // bf16 per smem row (80 B)
#define TILE_B (128 * TROW * 2)       // bytes per tile = 10240
#define BUF_B  (4 * TILE_B)           // Ah,Al,Bh,Bl = 40960
#define GEMM_SMEM (2 * BUF_B)         // 81920

__global__ void __launch_bounds__(256, 1)
gemm_tc(const __nv_bfloat16* __restrict__ Ah, const __nv_bfloat16* __restrict__ Al,
        const __nv_bfloat16* __restrict__ Bh, const __nv_bfloat16* __restrict__ Bl,
        const float* __restrict__ bias, const float* __restrict__ resid,
        float* __restrict__ Cout,
        __nv_bfloat16* __restrict__ outH, __nv_bfloat16* __restrict__ outL,
        int Nn, int Kk, int epi)
{
    extern __shared__ __align__(128) char smem[];
    const uint32_t sb = smem_u32(smem);

    const int tid  = threadIdx.x;
    const int wid  = tid >> 5;
    const int lane = tid & 31;
    const int bx = blockIdx.x;      // N tile
    const int by = blockIdx.y;      // M tile
    const int wm = wid & 3;         // 0..3: rows wm*32..+32
    const int wn = wid >> 2;        // 0..1: cols wn*64..+64

    // global bases
    const char* gA[2] = { (const char*)(Ah + (size_t)(by * 128) * Kk),
                          (const char*)(Al + (size_t)(by * 128) * Kk) };
    const char* gB[2] = { (const char*)(Bh + (size_t)(bx * 128) * Kk),
                          (const char*)(Bl + (size_t)(bx * 128) * Kk) };
    const size_t rowBytes = (size_t)Kk * 2;

    // loader mapping: 2 segments/thread/tile, each 16B
    const int r0 = tid >> 2;              // seg0 row 0..63
    const int c0 = (tid & 3) * 16;        // byte in 64B k-slab
    const int r1 = (tid + 256) >> 2;      // 64..127
    // smem tile offsets
    const uint32_t tAh = 0, tAl = TILE_B, tBh = 2 * TILE_B, tBl = 3 * TILE_B;

    // ldmatrix per-thread address components
    const uint32_t aRow  = (uint32_t)(wm * 32 + (lane & 15));
    const uint32_t aByte = (uint32_t)((lane >> 4) * 16);
    const uint32_t bRow  = (uint32_t)(wn * 64 + (lane & 7) + ((lane >> 4) << 3));
    const uint32_t bByte = (uint32_t)(((lane >> 3) & 1) * 16);

    float acc[2][8][4];
    #pragma unroll
    for (int mt = 0; mt < 2; mt++)
        #pragma unroll
        for (int nt = 0; nt < 8; nt++)
            #pragma unroll
            for (int e = 0; e < 4; e++) acc[mt][nt][e] = 0.f;

    const int nch = Kk >> 5;   // K/32

    // issue chunk 0
    {
        const uint32_t sbb = sb;
        const size_t kb = 0;
        cpa16(sbb + tAh + r0 * 80 + c0, gA[0] + (size_t)r0 * rowBytes + kb + c0);
        cpa16(sbb + tAh + r1 * 80 + c0, gA[0] + (size_t)r1 * rowBytes + kb + c0);
        cpa16(sbb + tAl + r0 * 80 + c0, gA[1] + (size_t)r0 * rowBytes + kb + c0);
        cpa16(sbb + tAl + r1 * 80 + c0, gA[1] + (size_t)r1 * rowBytes + kb + c0);
        cpa16(sbb + tBh + r0 * 80 + c0, gB[0] + (size_t)r0 * rowBytes + kb + c0);
        cpa16(sbb + tBh + r1 * 80 + c0, gB[0] + (size_t)r1 * rowBytes + kb + c0);
        cpa16(sbb + tBl + r0 * 80 + c0, gB[1] + (size_t)r0 * rowBytes + kb + c0);
        cpa16(sbb + tBl + r1 * 80 + c0, gB[1] + (size_t)r1 * rowBytes + kb + c0);
        CPA_COMMIT();
    }

    for (int c = 0; c < nch; c++) {
        if (c + 1 < nch) {
            const uint32_t sbb = sb + ((c + 1) & 1) * BUF_B;
            const size_t kb = (size_t)(c + 1) * 64;
            cpa16(sbb + tAh + r0 * 80 + c0, gA[0] + (size_t)r0 * rowBytes + kb + c0);
            cpa16(sbb + tAh + r1 * 80 + c0, gA[0] + (size_t)r1 * rowBytes + kb + c0);
            cpa16(sbb + tAl + r0 * 80 + c0, gA[1] + (size_t)r0 * rowBytes + kb + c0);
            cpa16(sbb + tAl + r1 * 80 + c0, gA[1] + (size_t)r1 * rowBytes + kb + c0);
            cpa16(sbb + tBh + r0 * 80 + c0, gB[0] + (size_t)r0 * rowBytes + kb + c0);
            cpa16(sbb + tBh + r1 * 80 + c0, gB[0] + (size_t)r1 * rowBytes + kb + c0);
            cpa16(sbb + tBl + r0 * 80 + c0, gB[1] + (size_t)r0 * rowBytes + kb + c0);
            cpa16(sbb + tBl + r1 * 80 + c0, gB[1] + (size_t)r1 * rowBytes + kb + c0);
            CPA_COMMIT();
            CPA_WAIT1();
        } else {
            CPA_WAIT0();
        }
        __syncthreads();

        const uint32_t buf = sb + (c & 1) * BUF_B;
        const uint32_t aHi = buf + tAh + aRow * 80 + aByte;
        const uint32_t aLo = buf + tAl + aRow * 80 + aByte;
        const uint32_t bHi = buf + tBh + bRow * 80 + bByte;
        const uint32_t bLo = buf + tBl + bRow * 80 + bByte;

        #pragma unroll
        for (int k16 = 0; k16 < 2; k16++) {
            const uint32_t ko = (uint32_t)(k16 * 32);
            uint32_t ah[2][4], al[2][4], bh[8][2], bl[8][2];
            ldm4(ah[0], aHi + ko);
            ldm4(ah[1], aHi + 16 * 80 + ko);
            ldm4(al[0], aLo + ko);
            ldm4(al[1], aLo + 16 * 80 + ko);
            #pragma unroll
            for (int p = 0; p < 4; p++) {
                uint32_t rh[4], rl[4];
                ldm4(rh, bHi + (uint32_t)(p * 16 * 80) + ko);
                ldm4(rl, bLo + (uint32_t)(p * 16 * 80) + ko);
                bh[2 * p][0] = rh[0]; bh[2 * p][1] = rh[1];
                bh[2 * p + 1][0] = rh[2]; bh[2 * p + 1][1] = rh[3];
                bl[2 * p][0] = rl[0]; bl[2 * p][1] = rl[1];
                bl[2 * p + 1][0] = rl[2]; bl[2 * p + 1][1] = rl[3];
            }
            #pragma unroll
            for (int mt = 0; mt < 2; mt++)
                #pragma unroll
                for (int nt = 0; nt < 8; nt++) {
                    mma16816(acc[mt][nt], ah[mt], bh[nt]);
                    mma16816(acc[mt][nt], ah[mt], bl[nt]);
                    mma16816(acc[mt][nt], al[mt], bh[nt]);
                }
        }
        __syncthreads();
    }

    // epilogue: thread owns (rowA, rowA+8) x (colp, colp+1) per (mt, nt)
    const int rowBase = by * 128 + wm * 32 + (lane >> 2);
    const int colBase = bx * 128 + wn * 64 + (lane & 3) * 2;
    #pragma unroll
    for (int mt = 0; mt < 2; mt++) {
        #pragma unroll
        for (int nt = 0; nt < 8; nt++) {
            const int col = colBase + nt * 8;
            const float b0 = bias[col], b1 = bias[col + 1];
            const int ra = rowBase + mt * 16;
            const int rb = ra + 8;
            float v00 = acc[mt][nt][0] + b0, v01 = acc[mt][nt][1] + b1;
            float v10 = acc[mt][nt][2] + b0, v11 = acc[mt][nt][3] + b1;
            if (epi == 1) {
                v00 = gelu_f(v00); v01 = gelu_f(v01);
                v10 = gelu_f(v10); v11 = gelu_f(v11);
                union { __nv_bfloat16 b2[2]; uint32_t u; } h0, l0, h1, l1;
                split_bf16(v00, h0.b2[0], l0.b2[0]);
                split_bf16(v01, h0.b2[1], l0.b2[1]);
                split_bf16(v10, h1.b2[0], l1.b2[0]);
                split_bf16(v11, h1.b2[1], l1.b2[1]);
                *(uint32_t*)&outH[(size_t)ra * Nn + col] = h0.u;
                *(uint32_t*)&outL[(size_t)ra * Nn + col] = l0.u;
                *(uint32_t*)&outH[(size_t)rb * Nn + col] = h1.u;
                *(uint32_t*)&outL[(size_t)rb * Nn + col] = l1.u;
            } else {
                if (epi == 2) {
                    const float2 r0v = *(const float2*)&resid[(size_t)ra * Nn + col];
                    const float2 r1v = *(const float2*)&resid[(size_t)rb * Nn + col];
                    v00 += r0v.x; v01 += r0v.y; v10 += r1v.x; v11 += r1v.y;
                }
                *(float2*)&Cout[(size_t)ra * Nn + col] = make_float2(v00, v01);
                *(float2*)&Cout[(size_t)rb * Nn + col] = make_float2(v10, v11);
            }
        }
    }
}

// ---------------------------------------------------------------------------
// Flash attention (fp32 SIMT, causal), register-tiled; emits bf16 hi/lo.
// ---------------------------------------------------------------------------
#define AS_ 68
#define ATTN_SMEM (4 * 64 * AS_ * 4)

__global__ void __launch_bounds__(256)
attn_kernel(const float* __restrict__ Q,
            const float* __restrict__ K,
            const float* __restrict__ V,
            __nv_bfloat16* __restrict__ Oh,
            __nv_bfloat16* __restrict__ Ol)
{
    extern __shared__ float sm[];
    float* Qs = sm;
    float* Ks = sm + 64 * AS_;
    float* Vs = sm + 2 * 64 * AS_;
    float* Ps = sm + 3 * 64 * AS_;

    const int qt  = blockIdx.x;
    const int h   = blockIdx.y;
    const int b   = blockIdx.z;
    const int tid = threadIdx.x;

    const int lrow = tid >> 2;
    const int lq4  = tid & 3;
    const int ty   = tid >> 4;
    const int tx   = tid & 15;

    const size_t base_q = ((size_t)(b * T_ + qt * 64)) * C_ + h * D_;
    #pragma unroll
    for (int i = 0; i < 4; i++) {
        int col = lq4 * 16 + i * 4;
        float4 qv = *(const float4*)&Q[base_q + (size_t)lrow * C_ + col];
        Qs[(col + 0) * AS_ + lrow] = qv.x;
        Qs[(col + 1) * AS_ + lrow] = qv.y;
        Qs[(col + 2) * AS_ + lrow] = qv.z;
        Qs[(col + 3) * AS_ + lrow] = qv.w;
    }

    float m[4], l[4], acc[4][4];
    #pragma unroll
    for (int i = 0; i < 4; i++) {
        m[i] = -1e30f; l[i] = 0.f;
        #pragma unroll
        for (int j = 0; j < 4; j++) acc[i][j] = 0.f;
    }

    for (int kt = 0; kt <= qt; kt++) {
        __syncthreads();
        const size_t base_k = ((size_t)(b * T_ + kt * 64)) * C_ + h * D_;
        #pragma unroll
        for (int i = 0; i < 4; i++) {
            int col = lq4 * 16 + i * 4;
            float4 kv = *(const float4*)&K[base_k + (size_t)lrow * C_ + col];
            Ks[(col + 0) * AS_ + lrow] = kv.x;
            Ks[(col + 1) * AS_ + lrow] = kv.y;
            Ks[(col + 2) * AS_ + lrow] = kv.z;
            Ks[(col + 3) * AS_ + lrow] = kv.w;
            float4 vv = *(const float4*)&V[base_k + (size_t)lrow * C_ + col];
            *(float4*)&Vs[lrow * AS_ + col] = vv;
        }
        __syncthreads();

        float s[4][4];
        #pragma unroll
        for (int i = 0; i < 4; i++)
            #pragma unroll
            for (int j = 0; j < 4; j++) s[i][j] = 0.f;
        #pragma unroll 8
        for (int d = 0; d < 64; d++) {
            float4 qf = *(const float4*)&Qs[d * AS_ + ty * 4];
            float4 kf = *(const float4*)&Ks[d * AS_ + tx * 4];
            float qa[4] = {qf.x, qf.y, qf.z, qf.w};
            float ka[4] = {kf.x, kf.y, kf.z, kf.w};
            #pragma unroll
            for (int i = 0; i < 4; i++)
                #pragma unroll
                for (int j = 0; j < 4; j++)
                    s[i][j] = fmaf(qa[i], ka[j], s[i][j]);
        }

        float corr[4];
        #pragma unroll
        for (int i = 0; i < 4; i++) {
            int qrow = qt * 64 + ty * 4 + i;
            float lm = -1e30f;
            #pragma unroll
            for (int j = 0; j < 4; j++) {
                int kcol = kt * 64 + tx * 4 + j;
                float t = s[i][j] * 0.125f;
                if (kcol > qrow) t = -1e30f;
                s[i][j] = t;
                lm = fmaxf(lm, t);
            }
            lm = fmaxf(lm, __shfl_xor_sync(0xffffffffu, lm, 1));
            lm = fmaxf(lm, __shfl_xor_sync(0xffffffffu, lm, 2));
            lm = fmaxf(lm, __shfl_xor_sync(0xffffffffu, lm, 4));
            lm = fmaxf(lm, __shfl_xor_sync(0xffffffffu, lm, 8));

            float mn = fmaxf(m[i], lm);
            corr[i]  = __expf(m[i] - mn);
            m[i]     = mn;

            float ls = 0.f;
            #pragma unroll
            for (int j = 0; j < 4; j++) {
                s[i][j] = __expf(s[i][j] - mn);
                ls += s[i][j];
            }
            ls += __shfl_xor_sync(0xffffffffu, ls, 1);
            ls += __shfl_xor_sync(0xffffffffu, ls, 2);
            ls += __shfl_xor_sync(0xffffffffu, ls, 4);
            ls += __shfl_xor_sync(0xffffffffu, ls, 8);
            l[i] = l[i] * corr[i] + ls;

            #pragma unroll
            for (int j = 0; j < 4; j++) acc[i][j] *= corr[i];
        }

        #pragma unroll
        for (int i = 0; i < 4; i++)
            #pragma unroll
            for (int j = 0; j < 4; j++)
                Ps[(tx * 4 + j) * AS_ + ty * 4 + i] = s[i][j];
        __syncthreads();

        #pragma unroll 8
        for (int k = 0; k < 64; k++) {
            float4 pf = *(const float4*)&Ps[k * AS_ + ty * 4];
            float4 vf = *(const float4*)&Vs[k * AS_ + tx * 4];
            float pa[4] = {pf.x, pf.y, pf.z, pf.w};
            float va[4] = {vf.x, vf.y, vf.z, vf.w};
            #pragma unroll
            for (int i = 0; i < 4; i++)
                #pragma unroll
                for (int j = 0; j < 4; j++)
                    acc[i][j] = fmaf(pa[i], va[j], acc[i][j]);
        }
    }

    #pragma unroll
    for (int i = 0; i < 4; i++) {
        float invl = 1.0f / l[i];
        size_t off = ((size_t)(b * T_ + qt * 64 + ty * 4 + i)) * C_ + h * D_ + tx * 4;
        union { __nv_bfloat16 b2[4]; uint2 u; } ph_, pl_;
        #pragma unroll
        for (int j = 0; j < 4; j++)
            split_bf16(acc[i][j] * invl, ph_.b2[j], pl_.b2[j]);
        *(uint2*)&Oh[off] = ph_.u;
        *(uint2*)&Ol[off] = pl_.u;
    }
}

// ---------------------------------------------------------------------------
// Launch
// ---------------------------------------------------------------------------
extern "C" void kernel_launch(void* const* d_in, const int* in_sizes, int n_in,
                              void* d_out, int out_size)
{
    const float* x      = (const float*)d_in[0];
    const float* Wq     = (const float*)d_in[1];
    const float* bq     = (const float*)d_in[2];
    const float* Wk     = (const float*)d_in[3];
    const float* bk     = (const float*)d_in[4];
    const float* Wv     = (const float*)d_in[5];
    const float* bv     = (const float*)d_in[6];
    const float* Wo     = (const float*)d_in[7];
    const float* bo     = (const float*)d_in[8];
    const float* ln1_g  = (const float*)d_in[9];
    const float* ln1_b  = (const float*)d_in[10];
    const float* ln2_g  = (const float*)d_in[11];
    const float* ln2_b  = (const float*)d_in[12];
    const float* W_fc   = (const float*)d_in[13];
    const float* b_fc   = (const float*)d_in[14];
    const float* W_proj = (const float*)d_in[15];
    const float* b_proj = (const float*)d_in[16];
    float* out = (float*)d_out;

    __nv_bfloat16 *lnh, *lnl, *atth, *attl, *fch, *fcl;
    __nv_bfloat16 *wqh, *wql, *wkh, *wkl, *wvh, *wvl, *woh, *wol, *wfh, *wfl, *wph, *wpl;
    float *q, *k, *v, *x1;
    cudaGetSymbolAddress((void**)&lnh,  g_lnh);  cudaGetSymbolAddress((void**)&lnl,  g_lnl);
    cudaGetSymbolAddress((void**)&atth, g_atth); cudaGetSymbolAddress((void**)&attl, g_attl);
    cudaGetSymbolAddress((void**)&fch,  g_fch);  cudaGetSymbolAddress((void**)&fcl,  g_fcl);
    cudaGetSymbolAddress((void**)&wqh,  g_wqh);  cudaGetSymbolAddress((void**)&wql,  g_wql);
    cudaGetSymbolAddress((void**)&wkh,  g_wkh);  cudaGetSymbolAddress((void**)&wkl,  g_wkl);
    cudaGetSymbolAddress((void**)&wvh,  g_wvh);  cudaGetSymbolAddress((void**)&wvl,  g_wvl);
    cudaGetSymbolAddress((void**)&woh,  g_woh);  cudaGetSymbolAddress((void**)&wol,  g_wol);
    cudaGetSymbolAddress((void**)&wfh,  g_wfh);  cudaGetSymbolAddress((void**)&wfl,  g_wfl);
    cudaGetSymbolAddress((void**)&wph,  g_wph);  cudaGetSymbolAddress((void**)&wpl,  g_wpl);
    cudaGetSymbolAddress((void**)&q,  g_q);
    cudaGetSymbolAddress((void**)&k,  g_k);
    cudaGetSymbolAddress((void**)&v,  g_v);
    cudaGetSymbolAddress((void**)&x1, g_x1);

    cudaFuncSetAttribute(attn_kernel, cudaFuncAttributeMaxDynamicSharedMemorySize, ATTN_SMEM);
    cudaFuncSetAttribute(gemm_tc,     cudaFuncAttributeMaxDynamicSharedMemorySize, GEMM_SMEM);

    // weight transpose + split
    dim3 wtb(256);
    wsplitT_kernel<<<dim3(C_/32,  C_/32),  wtb>>>(Wq,     wqh, wql, C_,  C_);
    wsplitT_kernel<<<dim3(C_/32,  C_/32),  wtb>>>(Wk,     wkh, wkl, C_,  C_);
    wsplitT_kernel<<<dim3(C_/32,  C_/32),  wtb>>>(Wv,     wvh, wvl, C_,  C_);
    wsplitT_kernel<<<dim3(C_/32,  C_/32),  wtb>>>(Wo,     woh, wol, C_,  C_);
    wsplitT_kernel<<<dim3(FC_/32, C_/32),  wtb>>>(W_fc,   wfh, wfl, C_,  FC_);
    wsplitT_kernel<<<dim3(C_/32,  FC_/32), wtb>>>(W_proj, wph, wpl, FC_, C_);

    dim3 gC(C_ / 128, M_ / 128);     // (8, 64)
    dim3 gF(FC_ / 128, M_ / 128);    // (32, 64)

    // 1) ln1
    ln_kernel<<<M_, 256>>>(x, ln1_g, ln1_b, lnh, lnl);
    // 2) q, k, v
    gemm_tc<<<gC, 256, GEMM_SMEM>>>(lnh, lnl, wqh, wql, bq, nullptr, q, nullptr, nullptr, C_, C_, 0);
    gemm_tc<<<gC, 256, GEMM_SMEM>>>(lnh, lnl, wkh, wkl, bk, nullptr, k, nullptr, nullptr, C_, C_, 0);
    gemm_tc<<<gC, 256, GEMM_SMEM>>>(lnh, lnl, wvh, wvl, bv, nullptr, v, nullptr, nullptr, C_, C_, 0);
    // 3) attention -> bf16 hi/lo
    attn_kernel<<<dim3(T_ / 64, H_, B_), 256, ATTN_SMEM>>>(q, k, v, atth, attl);
    // 4) x1 = x + att @ Wo + bo
    gemm_tc<<<gC, 256, GEMM_SMEM>>>(atth, attl, woh, wol, bo, x, x1, nullptr, nullptr, C_, C_, 2);
    // 5) ln2
    ln_kernel<<<M_, 256>>>(x1, ln2_g, ln2_b, lnh, lnl);
    // 6) fc = gelu(ln2 @ W_fc + b_fc) -> bf16 hi/lo
    gemm_tc<<<gF, 256, GEMM_SMEM>>>(lnh, lnl, wfh, wfl, b_fc, nullptr, nullptr, fch, fcl, FC_, C_, 1);
    // 7) out = x1 + fc @ W_proj + b_proj
    gemm_tc<<<gC, 256, GEMM_SMEM>>>(fch, fcl, wph, wpl, b_proj, x1, out, nullptr, nullptr, C_, FC_, 2);
}

// round 6
// speedup vs baseline: 3.8385x; 1.2955x over previous
#include <cuda_runtime.h>
#include <cuda_bf16.h>
#include <math.h>
#include <stdint.h>

// ---------------------------------------------------------------------------
// GPT block: B=4, T=2048, C=1024, H=16, D=64
// ---------------------------------------------------------------------------
#define B_  4
#define T_  2048
#define C_  1024
#define H_  16
#define D_  64
#define M_  (B_ * T_)      // 8192
#define FC_ (4 * C_)       // 4096

// ---------------------------------------------------------------------------
// Helpers
// ---------------------------------------------------------------------------
__device__ __forceinline__ uint32_t smem_u32(const void* p) {
    uint32_t a;
    asm("{ .reg .u64 t; cvta.to.shared.u64 t, %1; cvt.u32.u64 %0, t; }"
        : "=r"(a) : "l"(p));
    return a;
}

__device__ __forceinline__ void split_bf16(float v, __nv_bfloat16& h, __nv_bfloat16& l)
{
    h = __float2bfloat16(v);
    l = __float2bfloat16(v - __bfloat162float(h));
}

__device__ __forceinline__ uint32_t pack_split_hi(float a, float b) {
    __nv_bfloat162 t = __floats2bfloat162_rn(a, b);
    return *(uint32_t*)&t;
}
__device__ __forceinline__ uint32_t pack_split_lo(float a, float b) {
    __nv_bfloat16 ha = __float2bfloat16(a), hb = __float2bfloat16(b);
    __nv_bfloat162 t;
    t.x = __float2bfloat16(a - __bfloat162float(ha));
    t.y = __float2bfloat16(b - __bfloat162float(hb));
    return *(uint32_t*)&t;
}

__device__ __forceinline__ float gelu_f(float x)
{
    float x3 = x * x * x;
    return 0.5f * x * (1.0f + tanhf(0.7978845608028654f * (x + 0.044715f * x3)));
}

// cp.async 16B
__device__ __forceinline__ void cpa16(uint32_t s, const void* g) {
    asm volatile("cp.async.ca.shared.global [%0], [%1], 16;" :: "r"(s), "l"(g));
}
#define CPA_COMMIT() asm volatile("cp.async.commit_group;" ::: "memory")
#define CPA_WAIT1()  asm volatile("cp.async.wait_group 1;" ::: "memory")
#define CPA_WAIT0()  asm volatile("cp.async.wait_group 0;" ::: "memory")

// ldmatrix x4 (non-transposed)
__device__ __forceinline__ void ldm4(uint32_t* r, uint32_t addr) {
    asm volatile("ldmatrix.sync.aligned.m8n8.x4.shared.b16 {%0,%1,%2,%3}, [%4];"
        : "=r"(r[0]), "=r"(r[1]), "=r"(r[2]), "=r"(r[3]) : "r"(addr));
}

// mma m16n8k16 row.col f32.bf16.bf16.f32
__device__ __forceinline__ void mma16816(float* d, const uint32_t* a, const uint32_t* b) {
    asm volatile("mma.sync.aligned.m16n8k16.row.col.f32.bf16.bf16.f32 "
        "{%0,%1,%2,%3}, {%4,%5,%6,%7}, {%8,%9}, {%0,%1,%2,%3};"
        : "+f"(d[0]), "+f"(d[1]), "+f"(d[2]), "+f"(d[3])
        : "r"(a[0]), "r"(a[1]), "r"(a[2]), "r"(a[3]), "r"(b[0]), "r"(b[1]));
}

// ---------------------------------------------------------------------------
// Scratch (static __device__)
// ---------------------------------------------------------------------------
__device__ __align__(128) __nv_bfloat16 g_lnh [M_ * C_],  g_lnl [M_ * C_];
__device__ __align__(128) __nv_bfloat16 g_atth[M_ * C_],  g_attl[M_ * C_];
__device__ __align__(128) __nv_bfloat16 g_fch [M_ * FC_], g_fcl [M_ * FC_];
__device__ __align__(128) __nv_bfloat16 g_qh  [M_ * C_],  g_ql  [M_ * C_];
__device__ __align__(128) __nv_bfloat16 g_kh  [M_ * C_],  g_kl  [M_ * C_];
__device__ __align__(128) __nv_bfloat16 g_vh  [M_ * C_],  g_vl  [M_ * C_];
__device__ __align__(128) __nv_bfloat16 g_wqh [C_ * C_],  g_wql [C_ * C_];
__device__ __align__(128) __nv_bfloat16 g_wkh [C_ * C_],  g_wkl [C_ * C_];
__device__ __align__(128) __nv_bfloat16 g_wvh [C_ * C_],  g_wvl [C_ * C_];
__device__ __align__(128) __nv_bfloat16 g_woh [C_ * C_],  g_wol [C_ * C_];
__device__ __align__(128) __nv_bfloat16 g_wfh [FC_ * C_], g_wfl [FC_ * C_];
__device__ __align__(128) __nv_bfloat16 g_wph [C_ * FC_], g_wpl [C_ * FC_];
__device__ __align__(128) float g_x1[M_ * C_];

// ---------------------------------------------------------------------------
// Weight transpose + bf16 split: W[K][N] -> Th[N][K], Tl[N][K]
// ---------------------------------------------------------------------------
__global__ void wsplitT_kernel(const float* __restrict__ W,
                               __nv_bfloat16* __restrict__ Th,
                               __nv_bfloat16* __restrict__ Tl,
                               int K, int N)
{
    __shared__ float ts[32][33];
    int tx = threadIdx.x & 31, ty = threadIdx.x >> 5;
    int bx = blockIdx.x, by = blockIdx.y;
    #pragma unroll
    for (int i = 0; i < 4; i++) {
        int k = by * 32 + ty + i * 8;
        ts[ty + i * 8][tx] = W[(size_t)k * N + bx * 32 + tx];
    }
    __syncthreads();
    #pragma unroll
    for (int i = 0; i < 4; i++) {
        int n = bx * 32 + ty + i * 8;
        int k = by * 32 + tx;
        float v = ts[tx][ty + i * 8];
        __nv_bfloat16 h, l; split_bf16(v, h, l);
        Th[(size_t)n * K + k] = h;
        Tl[(size_t)n * K + k] = l;
    }
}

// ---------------------------------------------------------------------------
// LayerNorm -> bf16 hi/lo
// ---------------------------------------------------------------------------
__global__ void ln_kernel(const float* __restrict__ x,
                          const float* __restrict__ gamma,
                          const float* __restrict__ beta,
                          __nv_bfloat16* __restrict__ yh,
                          __nv_bfloat16* __restrict__ yl)
{
    int row = blockIdx.x;
    int t   = threadIdx.x;
    const float4* xr = (const float4*)(x + (size_t)row * C_);
    float4 xv = xr[t];

    float s  = xv.x + xv.y + xv.z + xv.w;
    float ss = fmaf(xv.x, xv.x, fmaf(xv.y, xv.y, fmaf(xv.z, xv.z, xv.w * xv.w)));
    #pragma unroll
    for (int o = 16; o > 0; o >>= 1) {
        s  += __shfl_xor_sync(0xffffffffu, s,  o);
        ss += __shfl_xor_sync(0xffffffffu, ss, o);
    }
    __shared__ float rs[8], rss[8];
    __shared__ float s_mu, s_inv;
    int w = t >> 5, lane = t & 31;
    if (lane == 0) { rs[w] = s; rss[w] = ss; }
    __syncthreads();
    if (t == 0) {
        float ts = 0.f, tss = 0.f;
        #pragma unroll
        for (int i = 0; i < 8; i++) { ts += rs[i]; tss += rss[i]; }
        float mu  = ts * (1.0f / (float)C_);
        float var = tss * (1.0f / (float)C_) - mu * mu;
        s_mu = mu;  s_inv = rsqrtf(var + 1e-5f);
    }
    __syncthreads();
    float mu = s_mu, inv = s_inv;

    float4 gv = ((const float4*)gamma)[t];
    float4 bv = ((const float4*)beta)[t];
    float o[4];
    o[0] = (xv.x - mu) * inv * gv.x + bv.x;
    o[1] = (xv.y - mu) * inv * gv.y + bv.y;
    o[2] = (xv.z - mu) * inv * gv.z + bv.z;
    o[3] = (xv.w - mu) * inv * gv.w + bv.w;

    union { __nv_bfloat16 b[4]; uint2 u; } ph, pl;
    #pragma unroll
    for (int i = 0; i < 4; i++) split_bf16(o[i], ph.b[i], pl.b[i]);
    ((uint2*)(yh + (size_t)row * C_))[t] = ph.u;
    ((uint2*)(yl + (size_t)row * C_))[t] = pl.u;
}

// ---------------------------------------------------------------------------
// Tensor-core GEMM via mma.sync (split-bf16 x3, fp32 accum)
//   epi 0: out fp32 = acc + bias
//   epi 1: outH/outL bf16 = split(gelu(acc + bias))
//   epi 2: out fp32 = acc + bias + resid
//   epi 3: outH/outL bf16 = split(acc + bias)
// ---------------------------------------------------------------------------
#define TROW 40
#define TILE_B (128 * TROW * 2)       // 10240
#define BUF_B  (4 * TILE_B)           // 40960
#define GEMM_SMEM (2 * BUF_B)         // 81920

__global__ void __launch_bounds__(256, 1)
gemm_tc(const __nv_bfloat16* __restrict__ Ah, const __nv_bfloat16* __restrict__ Al,
        const __nv_bfloat16* __restrict__ Bh, const __nv_bfloat16* __restrict__ Bl,
        const float* __restrict__ bias, const float* __restrict__ resid,
        float* __restrict__ Cout,
        __nv_bfloat16* __restrict__ outH, __nv_bfloat16* __restrict__ outL,
        int Nn, int Kk, int epi)
{
    extern __shared__ __align__(128) char smem[];
    const uint32_t sb = smem_u32(smem);

    const int tid  = threadIdx.x;
    const int wid  = tid >> 5;
    const int lane = tid & 31;
    const int bx = blockIdx.x;
    const int by = blockIdx.y;
    const int wm = wid & 3;
    const int wn = wid >> 2;

    const char* gA[2] = { (const char*)(Ah + (size_t)(by * 128) * Kk),
                          (const char*)(Al + (size_t)(by * 128) * Kk) };
    const char* gB[2] = { (const char*)(Bh + (size_t)(bx * 128) * Kk),
                          (const char*)(Bl + (size_t)(bx * 128) * Kk) };
    const size_t rowBytes = (size_t)Kk * 2;

    const int r0 = tid >> 2;
    const int c0 = (tid & 3) * 16;
    const int r1 = (tid + 256) >> 2;
    const uint32_t tAh = 0, tAl = TILE_B, tBh = 2 * TILE_B, tBl = 3 * TILE_B;

    const uint32_t aRow  = (uint32_t)(wm * 32 + (lane & 15));
    const uint32_t aByte = (uint32_t)((lane >> 4) * 16);
    const uint32_t bRow  = (uint32_t)(wn * 64 + (lane & 7) + ((lane >> 4) << 3));
    const uint32_t bByte = (uint32_t)(((lane >> 3) & 1) * 16);

    float acc[2][8][4];
    #pragma unroll
    for (int mt = 0; mt < 2; mt++)
        #pragma unroll
        for (int nt = 0; nt < 8; nt++)
            #pragma unroll
            for (int e = 0; e < 4; e++) acc[mt][nt][e] = 0.f;

    const int nch = Kk >> 5;

    {
        const uint32_t sbb = sb;
        cpa16(sbb + tAh + r0 * 80 + c0, gA[0] + (size_t)r0 * rowBytes + c0);
        cpa16(sbb + tAh + r1 * 80 + c0, gA[0] + (size_t)r1 * rowBytes + c0);
        cpa16(sbb + tAl + r0 * 80 + c0, gA[1] + (size_t)r0 * rowBytes + c0);
        cpa16(sbb + tAl + r1 * 80 + c0, gA[1] + (size_t)r1 * rowBytes + c0);
        cpa16(sbb + tBh + r0 * 80 + c0, gB[0] + (size_t)r0 * rowBytes + c0);
        cpa16(sbb + tBh + r1 * 80 + c0, gB[0] + (size_t)r1 * rowBytes + c0);
        cpa16(sbb + tBl + r0 * 80 + c0, gB[1] + (size_t)r0 * rowBytes + c0);
        cpa16(sbb + tBl + r1 * 80 + c0, gB[1] + (size_t)r1 * rowBytes + c0);
        CPA_COMMIT();
    }

    for (int c = 0; c < nch; c++) {
        if (c + 1 < nch) {
            const uint32_t sbb = sb + ((c + 1) & 1) * BUF_B;
            const size_t kb = (size_t)(c + 1) * 64;
            cpa16(sbb + tAh + r0 * 80 + c0, gA[0] + (size_t)r0 * rowBytes + kb + c0);
            cpa16(sbb + tAh + r1 * 80 + c0, gA[0] + (size_t)r1 * rowBytes + kb + c0);
            cpa16(sbb + tAl + r0 * 80 + c0, gA[1] + (size_t)r0 * rowBytes + kb + c0);
            cpa16(sbb + tAl + r1 * 80 + c0, gA[1] + (size_t)r1 * rowBytes + kb + c0);
            cpa16(sbb + tBh + r0 * 80 + c0, gB[0] + (size_t)r0 * rowBytes + kb + c0);
            cpa16(sbb + tBh + r1 * 80 + c0, gB[0] + (size_t)r1 * rowBytes + kb + c0);
            cpa16(sbb + tBl + r0 * 80 + c0, gB[1] + (size_t)r0 * rowBytes + kb + c0);
            cpa16(sbb + tBl + r1 * 80 + c0, gB[1] + (size_t)r1 * rowBytes + kb + c0);
            CPA_COMMIT();
            CPA_WAIT1();
        } else {
            CPA_WAIT0();
        }
        __syncthreads();

        const uint32_t buf = sb + (c & 1) * BUF_B;
        const uint32_t aHi = buf + tAh + aRow * 80 + aByte;
        const uint32_t aLo = buf + tAl + aRow * 80 + aByte;
        const uint32_t bHi = buf + tBh + bRow * 80 + bByte;
        const uint32_t bLo = buf + tBl + bRow * 80 + bByte;

        #pragma unroll
        for (int k16 = 0; k16 < 2; k16++) {
            const uint32_t ko = (uint32_t)(k16 * 32);
            uint32_t ah[2][4], al[2][4], bh[8][2], bl[8][2];
            ldm4(ah[0], aHi + ko);
            ldm4(ah[1], aHi + 16 * 80 + ko);
            ldm4(al[0], aLo + ko);
            ldm4(al[1], aLo + 16 * 80 + ko);
            #pragma unroll
            for (int p = 0; p < 4; p++) {
                uint32_t rh[4], rl[4];
                ldm4(rh, bHi + (uint32_t)(p * 16 * 80) + ko);
                ldm4(rl, bLo + (uint32_t)(p * 16 * 80) + ko);
                bh[2 * p][0] = rh[0]; bh[2 * p][1] = rh[1];
                bh[2 * p + 1][0] = rh[2]; bh[2 * p + 1][1] = rh[3];
                bl[2 * p][0] = rl[0]; bl[2 * p][1] = rl[1];
                bl[2 * p + 1][0] = rl[2]; bl[2 * p + 1][1] = rl[3];
            }
            #pragma unroll
            for (int mt = 0; mt < 2; mt++)
                #pragma unroll
                for (int nt = 0; nt < 8; nt++) {
                    mma16816(acc[mt][nt], ah[mt], bh[nt]);
                    mma16816(acc[mt][nt], ah[mt], bl[nt]);
                    mma16816(acc[mt][nt], al[mt], bh[nt]);
                }
        }
        __syncthreads();
    }

    const int rowBase = by * 128 + wm * 32 + (lane >> 2);
    const int colBase = bx * 128 + wn * 64 + (lane & 3) * 2;
    #pragma unroll
    for (int mt = 0; mt < 2; mt++) {
        #pragma unroll
        for (int nt = 0; nt < 8; nt++) {
            const int col = colBase + nt * 8;
            const float b0 = bias[col], b1 = bias[col + 1];
            const int ra = rowBase + mt * 16;
            const int rb = ra + 8;
            float v00 = acc[mt][nt][0] + b0, v01 = acc[mt][nt][1] + b1;
            float v10 = acc[mt][nt][2] + b0, v11 = acc[mt][nt][3] + b1;
            if (epi == 1 || epi == 3) {
                if (epi == 1) {
                    v00 = gelu_f(v00); v01 = gelu_f(v01);
                    v10 = gelu_f(v10); v11 = gelu_f(v11);
                }
                *(uint32_t*)&outH[(size_t)ra * Nn + col] = pack_split_hi(v00, v01);
                *(uint32_t*)&outL[(size_t)ra * Nn + col] = pack_split_lo(v00, v01);
                *(uint32_t*)&outH[(size_t)rb * Nn + col] = pack_split_hi(v10, v11);
                *(uint32_t*)&outL[(size_t)rb * Nn + col] = pack_split_lo(v10, v11);
            } else {
                if (epi == 2) {
                    const float2 r0v = *(const float2*)&resid[(size_t)ra * Nn + col];
                    const float2 r1v = *(const float2*)&resid[(size_t)rb * Nn + col];
                    v00 += r0v.x; v01 += r0v.y; v10 += r1v.x; v11 += r1v.y;
                }
                *(float2*)&Cout[(size_t)ra * Nn + col] = make_float2(v00, v01);
                *(float2*)&Cout[(size_t)rb * Nn + col] = make_float2(v10, v11);
            }
        }
    }
}

// ---------------------------------------------------------------------------
// Tensor-core flash attention (split-bf16 x3, causal).
// CTA = 128 queries x head; 8 warps x m16. K tiles of 64 keys.
// Q/K smem row-major [seq][d], stride 72 bf16 (144B) - ldmatrix conflict-free.
// V stored TRANSPOSED in smem: Vt[d][key], so PV uses the same non-trans
// ldmatrix B path as gemm_tc. P converted to A-frags in registers.
// ---------------------------------------------------------------------------
#define STR_ 72
#define SQ_BYTES (128 * STR_ * 2)
#define SK_BYTES (64 * STR_ * 2)
#define ATTN_SMEM (2 * SQ_BYTES + 4 * SK_BYTES)   // 73728

__global__ void __launch_bounds__(256, 1)
attn_tc(const __nv_bfloat16* __restrict__ Qh_, const __nv_bfloat16* __restrict__ Ql_,
        const __nv_bfloat16* __restrict__ Kh_, const __nv_bfloat16* __restrict__ Kl_,
        const __nv_bfloat16* __restrict__ Vh_, const __nv_bfloat16* __restrict__ Vl_,
        __nv_bfloat16* __restrict__ Oh_, __nv_bfloat16* __restrict__ Ol_)
{
    extern __shared__ __align__(128) char smem[];
    const uint32_t sQh = smem_u32(smem);
    const uint32_t sQl = sQh + SQ_BYTES;
    const uint32_t sKh = sQl + SQ_BYTES;
    const uint32_t sKl = sKh + SK_BYTES;
    const uint32_t sVh = sKl + SK_BYTES;
    const uint32_t sVl = sVh + SK_BYTES;
    __nv_bfloat16* mVh = (__nv_bfloat16*)(smem + 2 * SQ_BYTES + 2 * SK_BYTES);
    __nv_bfloat16* mVl = (__nv_bfloat16*)(smem + 2 * SQ_BYTES + 3 * SK_BYTES);

    const int qt = blockIdx.x, h = blockIdx.y, b = blockIdx.z;
    const int tid = threadIdx.x, wid = tid >> 5, lane = tid & 31;
    const int wm = wid;                      // warp owns rows wm*16..+15

    const size_t rowB = (size_t)C_ * 2;      // global row bytes
    const size_t qbase = ((size_t)(b * T_ + qt * 128)) * rowB + (size_t)h * 128;

    // issue Q loads (128 rows x 128B, hi+lo)
    #pragma unroll
    for (int i = 0; i < 4; i++) {
        int c = tid + i * 256;               // 0..1023
        int r = c >> 3, ch = (c & 7) * 16;
        cpa16(sQh + r * 144 + ch, (const char*)Qh_ + qbase + (size_t)r * rowB + ch);
        cpa16(sQl + r * 144 + ch, (const char*)Ql_ + qbase + (size_t)r * rowB + ch);
    }
    CPA_COMMIT();

    // fragment address components (same mapping as gemm_tc)
    const uint32_t aOff  = (uint32_t)((wm * 16 + (lane & 15)) * 144 + (lane >> 4) * 16);
    const uint32_t bRow  = (uint32_t)((lane & 7) + ((lane >> 4) << 3));
    const uint32_t bByte = (uint32_t)(((lane >> 3) & 1) * 16);

    uint32_t qh[4][4], ql[4][4];
    float oacc[8][4];
    #pragma unroll
    for (int nd = 0; nd < 8; nd++)
        #pragma unroll
        for (int e = 0; e < 4; e++) oacc[nd][e] = 0.f;
    float m0 = -1e30f, m1 = -1e30f, l0 = 0.f, l1 = 0.f;

    const int qr0 = qt * 128 + wm * 16 + (lane >> 2);
    const int nkt = 2 * qt + 2;

    for (int kt = 0; kt < nkt; kt++) {
        __syncthreads();   // all warps done reading previous K/V tiles
        const size_t kbase = ((size_t)(b * T_ + kt * 64)) * rowB + (size_t)h * 128;
        #pragma unroll
        for (int i = 0; i < 2; i++) {
            int c = tid + i * 256;           // 0..511
            int r = c >> 3, ch = (c & 7) * 16;
            cpa16(sKh + r * 144 + ch, (const char*)Kh_ + kbase + (size_t)r * rowB + ch);
            cpa16(sKl + r * 144 + ch, (const char*)Kl_ + kbase + (size_t)r * rowB + ch);
        }
        CPA_COMMIT();

        // V -> registers (for transposed smem store)
        uint4 vregH[2], vregL[2];
        int vkey[2], vd0[2];
        #pragma unroll
        for (int i = 0; i < 2; i++) {
            int c = tid + i * 256;           // 0..511
            vkey[i] = c & 63;
            vd0[i]  = (c >> 6) * 8;
            const char* src = (const char*)Vh_ + kbase + (size_t)vkey[i] * rowB + (c >> 6) * 16;
            vregH[i] = *(const uint4*)src;
            const char* srcl = (const char*)Vl_ + kbase + (size_t)vkey[i] * rowB + (c >> 6) * 16;
            vregL[i] = *(const uint4*)srcl;
        }

        CPA_WAIT0();   // Q (iter 0) + K tile ready

        // store V transposed: Vt[d][key]
        #pragma unroll
        for (int i = 0; i < 2; i++) {
            const __nv_bfloat16* eh = (const __nv_bfloat16*)&vregH[i];
            const __nv_bfloat16* el = (const __nv_bfloat16*)&vregL[i];
            #pragma unroll
            for (int j = 0; j < 8; j++) {
                mVh[(vd0[i] + j) * STR_ + vkey[i]] = eh[j];
                mVl[(vd0[i] + j) * STR_ + vkey[i]] = el[j];
            }
        }
        __syncthreads();

        if (kt == 0) {
            #pragma unroll
            for (int ks = 0; ks < 4; ks++) {
                ldm4(qh[ks], sQh + aOff + ks * 32);
                ldm4(ql[ks], sQl + aOff + ks * 32);
            }
        }

        // ---- S = Q . K^T (split x3) ----
        float sa[8][4];
        #pragma unroll
        for (int nt = 0; nt < 8; nt++)
            #pragma unroll
            for (int e = 0; e < 4; e++) sa[nt][e] = 0.f;

        #pragma unroll
        for (int ks = 0; ks < 4; ks++) {
            uint32_t bh[8][2], bl[8][2];
            #pragma unroll
            for (int p = 0; p < 4; p++) {
                uint32_t rh[4], rl[4];
                ldm4(rh, sKh + (p * 16 + bRow) * 144 + bByte + ks * 32);
                ldm4(rl, sKl + (p * 16 + bRow) * 144 + bByte + ks * 32);
                bh[2 * p][0] = rh[0]; bh[2 * p][1] = rh[1];
                bh[2 * p + 1][0] = rh[2]; bh[2 * p + 1][1] = rh[3];
                bl[2 * p][0] = rl[0]; bl[2 * p][1] = rl[1];
                bl[2 * p + 1][0] = rl[2]; bl[2 * p + 1][1] = rl[3];
            }
            #pragma unroll
            for (int nt = 0; nt < 8; nt++) {
                mma16816(sa[nt], qh[ks], bh[nt]);
                mma16816(sa[nt], qh[ks], bl[nt]);
                mma16816(sa[nt], ql[ks], bh[nt]);
            }
        }

        // ---- online softmax ----
        float tm0 = -1e30f, tm1 = -1e30f;
        #pragma unroll
        for (int nt = 0; nt < 8; nt++) {
            #pragma unroll
            for (int j = 0; j < 2; j++) {
                int kcol = kt * 64 + nt * 8 + (lane & 3) * 2 + j;
                float s0 = sa[nt][j] * 0.125f;
                float s1 = sa[nt][2 + j] * 0.125f;
                if (kcol > qr0)     s0 = -1e30f;
                if (kcol > qr0 + 8) s1 = -1e30f;
                sa[nt][j] = s0;  sa[nt][2 + j] = s1;
                tm0 = fmaxf(tm0, s0);  tm1 = fmaxf(tm1, s1);
            }
        }
        tm0 = fmaxf(tm0, __shfl_xor_sync(0xffffffffu, tm0, 1));
        tm0 = fmaxf(tm0, __shfl_xor_sync(0xffffffffu, tm0, 2));
        tm1 = fmaxf(tm1, __shfl_xor_sync(0xffffffffu, tm1, 1));
        tm1 = fmaxf(tm1, __shfl_xor_sync(0xffffffffu, tm1, 2));

        const float nm0 = fmaxf(m0, tm0), nm1 = fmaxf(m1, tm1);
        const float cr0 = __expf(m0 - nm0), cr1 = __expf(m1 - nm1);
        m0 = nm0; m1 = nm1;

        float rs0 = 0.f, rs1 = 0.f;
        #pragma unroll
        for (int nt = 0; nt < 8; nt++) {
            #pragma unroll
            for (int j = 0; j < 2; j++) {
                float p0 = __expf(sa[nt][j] - m0);
                float p1 = __expf(sa[nt][2 + j] - m1);
                sa[nt][j] = p0;  sa[nt][2 + j] = p1;
                rs0 += p0;  rs1 += p1;
            }
        }
        rs0 += __shfl_xor_sync(0xffffffffu, rs0, 1);
        rs0 += __shfl_xor_sync(0xffffffffu, rs0, 2);
        rs1 += __shfl_xor_sync(0xffffffffu, rs1, 1);
        rs1 += __shfl_xor_sync(0xffffffffu, rs1, 2);
        l0 = l0 * cr0 + rs0;
        l1 = l1 * cr1 + rs1;

        #pragma unroll
        for (int nd = 0; nd < 8; nd++) {
            oacc[nd][0] *= cr0; oacc[nd][1] *= cr0;
            oacc[nd][2] *= cr1; oacc[nd][3] *= cr1;
        }

        // ---- P -> A-frags (hi/lo), in registers ----
        uint32_t pH[4][4], pL[4][4];
        #pragma unroll
        for (int ks = 0; ks < 4; ks++) {
            const int t0 = 2 * ks, t1 = 2 * ks + 1;
            pH[ks][0] = pack_split_hi(sa[t0][0], sa[t0][1]);
            pL[ks][0] = pack_split_lo(sa[t0][0], sa[t0][1]);
            pH[ks][1] = pack_split_hi(sa[t0][2], sa[t0][3]);
            pL[ks][1] = pack_split_lo(sa[t0][2], sa[t0][3]);
            pH[ks][2] = pack_split_hi(sa[t1][0], sa[t1][1]);
            pL[ks][2] = pack_split_lo(sa[t1][0], sa[t1][1]);
            pH[ks][3] = pack_split_hi(sa[t1][2], sa[t1][3]);
            pL[ks][3] = pack_split_lo(sa[t1][2], sa[t1][3]);
        }

        // ---- O += P . V (split x3) ----
        #pragma unroll
        for (int ks = 0; ks < 4; ks++) {
            uint32_t vh[8][2], vl[8][2];
            #pragma unroll
            for (int p = 0; p < 4; p++) {
                uint32_t rh[4], rl[4];
                ldm4(rh, sVh + (p * 16 + bRow) * 144 + bByte + ks * 32);
                ldm4(rl, sVl + (p * 16 + bRow) * 144 + bByte + ks * 32);
                vh[2 * p][0] = rh[0]; vh[2 * p][1] = rh[1];
                vh[2 * p + 1][0] = rh[2]; vh[2 * p + 1][1] = rh[3];
                vl[2 * p][0] = rl[0]; vl[2 * p][1] = rl[1];
                vl[2 * p + 1][0] = rl[2]; vl[2 * p + 1][1] = rl[3];
            }
            #pragma unroll
            for (int nd = 0; nd < 8; nd++) {
                mma16816(oacc[nd], pH[ks], vh[nd]);
                mma16816(oacc[nd], pH[ks], vl[nd]);
                mma16816(oacc[nd], pL[ks], vh[nd]);
            }
        }
    }

    // ---- epilogue ----
    const float il0 = 1.0f / l0, il1 = 1.0f / l1;
    const size_t tok0 = (size_t)(b * T_ + qt * 128 + wm * 16 + (lane >> 2));
    const int colb = h * 64 + (lane & 3) * 2;
    #pragma unroll
    for (int nd = 0; nd < 8; nd++) {
        const int col = colb + nd * 8;
        float v00 = oacc[nd][0] * il0, v01 = oacc[nd][1] * il0;
        float v10 = oacc[nd][2] * il1, v11 = oacc[nd][3] * il1;
        *(uint32_t*)&Oh_[tok0 * C_ + col]       = pack_split_hi(v00, v01);
        *(uint32_t*)&Ol_[tok0 * C_ + col]       = pack_split_lo(v00, v01);
        *(uint32_t*)&Oh_[(tok0 + 8) * C_ + col] = pack_split_hi(v10, v11);
        *(uint32_t*)&Ol_[(tok0 + 8) * C_ + col] = pack_split_lo(v10, v11);
    }
}

// ---------------------------------------------------------------------------
// Launch
// ---------------------------------------------------------------------------
extern "C" void kernel_launch(void* const* d_in, const int* in_sizes, int n_in,
                              void* d_out, int out_size)
{
    const float* x      = (const float*)d_in[0];
    const float* Wq     = (const float*)d_in[1];
    const float* bq     = (const float*)d_in[2];
    const float* Wk     = (const float*)d_in[3];
    const float* bk     = (const float*)d_in[4];
    const float* Wv     = (const float*)d_in[5];
    const float* bv     = (const float*)d_in[6];
    const float* Wo     = (const float*)d_in[7];
    const float* bo     = (const float*)d_in[8];
    const float* ln1_g  = (const float*)d_in[9];
    const float* ln1_b  = (const float*)d_in[10];
    const float* ln2_g  = (const float*)d_in[11];
    const float* ln2_b  = (const float*)d_in[12];
    const float* W_fc   = (const float*)d_in[13];
    const float* b_fc   = (const float*)d_in[14];
    const float* W_proj = (const float*)d_in[15];
    const float* b_proj = (const float*)d_in[16];
    float* out = (float*)d_out;

    __nv_bfloat16 *lnh, *lnl, *atth, *attl, *fch, *fcl;
    __nv_bfloat16 *qh, *ql, *kh, *kl, *vh, *vl;
    __nv_bfloat16 *wqh, *wql, *wkh, *wkl, *wvh, *wvl, *woh, *wol, *wfh, *wfl, *wph, *wpl;
    float *x1;
    cudaGetSymbolAddress((void**)&lnh,  g_lnh);  cudaGetSymbolAddress((void**)&lnl,  g_lnl);
    cudaGetSymbolAddress((void**)&atth, g_atth); cudaGetSymbolAddress((void**)&attl, g_attl);
    cudaGetSymbolAddress((void**)&fch,  g_fch);  cudaGetSymbolAddress((void**)&fcl,  g_fcl);
    cudaGetSymbolAddress((void**)&qh,   g_qh);   cudaGetSymbolAddress((void**)&ql,   g_ql);
    cudaGetSymbolAddress((void**)&kh,   g_kh);   cudaGetSymbolAddress((void**)&kl,   g_kl);
    cudaGetSymbolAddress((void**)&vh,   g_vh);   cudaGetSymbolAddress((void**)&vl,   g_vl);
    cudaGetSymbolAddress((void**)&wqh,  g_wqh);  cudaGetSymbolAddress((void**)&wql,  g_wql);
    cudaGetSymbolAddress((void**)&wkh,  g_wkh);  cudaGetSymbolAddress((void**)&wkl,  g_wkl);
    cudaGetSymbolAddress((void**)&wvh,  g_wvh);  cudaGetSymbolAddress((void**)&wvl,  g_wvl);
    cudaGetSymbolAddress((void**)&woh,  g_woh);  cudaGetSymbolAddress((void**)&wol,  g_wol);
    cudaGetSymbolAddress((void**)&wfh,  g_wfh);  cudaGetSymbolAddress((void**)&wfl,  g_wfl);
    cudaGetSymbolAddress((void**)&wph,  g_wph);  cudaGetSymbolAddress((void**)&wpl,  g_wpl);
    cudaGetSymbolAddress((void**)&x1, g_x1);

    cudaFuncSetAttribute(attn_tc, cudaFuncAttributeMaxDynamicSharedMemorySize, ATTN_SMEM);
    cudaFuncSetAttribute(gemm_tc, cudaFuncAttributeMaxDynamicSharedMemorySize, GEMM_SMEM);

    dim3 wtb(256);
    wsplitT_kernel<<<dim3(C_/32,  C_/32),  wtb>>>(Wq,     wqh, wql, C_,  C_);
    wsplitT_kernel<<<dim3(C_/32,  C_/32),  wtb>>>(Wk,     wkh, wkl, C_,  C_);
    wsplitT_kernel<<<dim3(C_/32,  C_/32),  wtb>>>(Wv,     wvh, wvl, C_,  C_);
    wsplitT_kernel<<<dim3(C_/32,  C_/32),  wtb>>>(Wo,     woh, wol, C_,  C_);
    wsplitT_kernel<<<dim3(FC_/32, C_/32),  wtb>>>(W_fc,   wfh, wfl, C_,  FC_);
    wsplitT_kernel<<<dim3(C_/32,  FC_/32), wtb>>>(W_proj, wph, wpl, FC_, C_);

    dim3 gC(C_ / 128, M_ / 128);     // (8, 64)
    dim3 gF(FC_ / 128, M_ / 128);    // (32, 64)

    // 1) ln1
    ln_kernel<<<M_, 256>>>(x, ln1_g, ln1_b, lnh, lnl);
    // 2) q, k, v -> bf16 hi/lo directly (epi 3)
    gemm_tc<<<gC, 256, GEMM_SMEM>>>(lnh, lnl, wqh, wql, bq, nullptr, nullptr, qh, ql, C_, C_, 3);
    gemm_tc<<<gC, 256, GEMM_SMEM>>>(lnh, lnl, wkh, wkl, bk, nullptr, nullptr, kh, kl, C_, C_, 3);
    gemm_tc<<<gC, 256, GEMM_SMEM>>>(lnh, lnl, wvh, wvl, bv, nullptr, nullptr, vh, vl, C_, C_, 3);
    // 3) tensor-core attention -> bf16 hi/lo
    attn_tc<<<dim3(T_ / 128, H_, B_), 256, ATTN_SMEM>>>(qh, ql, kh, kl, vh, vl, atth, attl);
    // 4) x1 = x + att @ Wo + bo
    gemm_tc<<<gC, 256, GEMM_SMEM>>>(atth, attl, woh, wol, bo, x, x1, nullptr, nullptr, C_, C_, 2);
    // 5) ln2
    ln_kernel<<<M_, 256>>>(x1, ln2_g, ln2_b, lnh, lnl);
    // 6) fc = gelu(ln2 @ W_fc + b_fc) -> bf16 hi/lo
    gemm_tc<<<gF, 256, GEMM_SMEM>>>(lnh, lnl, wfh, wfl, b_fc, nullptr, nullptr, fch, fcl, FC_, C_, 1);
    // 7) out = x1 + fc @ W_proj + b_proj
    gemm_tc<<<gC, 256, GEMM_SMEM>>>(fch, fcl, wph, wpl, b_proj, x1, out, nullptr, nullptr, C_, FC_, 2);
}

// round 7
// speedup vs baseline: 4.2005x; 1.0943x over previous
#include <cuda_runtime.h>
#include <cuda_bf16.h>
#include <math.h>
#include <stdint.h>

// ---------------------------------------------------------------------------
// GPT block: B=4, T=2048, C=1024, H=16, D=64
// ---------------------------------------------------------------------------
#define B_  4
#define T_  2048
#define C_  1024
#define C3_ (3 * C_)
#define H_  16
#define D_  64
#define M_  (B_ * T_)      // 8192
#define FC_ (4 * C_)       // 4096

// ---------------------------------------------------------------------------
// Helpers
// ---------------------------------------------------------------------------
__device__ __forceinline__ uint32_t smem_u32(const void* p) {
    uint32_t a;
    asm("{ .reg .u64 t; cvta.to.shared.u64 t, %1; cvt.u32.u64 %0, t; }"
        : "=r"(a) : "l"(p));
    return a;
}

__device__ __forceinline__ void split_bf16(float v, __nv_bfloat16& h, __nv_bfloat16& l)
{
    h = __float2bfloat16(v);
    l = __float2bfloat16(v - __bfloat162float(h));
}

__device__ __forceinline__ uint32_t pack_split_hi(float a, float b) {
    __nv_bfloat162 t = __floats2bfloat162_rn(a, b);
    return *(uint32_t*)&t;
}
__device__ __forceinline__ uint32_t pack_split_lo(float a, float b) {
    __nv_bfloat16 ha = __float2bfloat16(a), hb = __float2bfloat16(b);
    __nv_bfloat162 t;
    t.x = __float2bfloat16(a - __bfloat162float(ha));
    t.y = __float2bfloat16(b - __bfloat162float(hb));
    return *(uint32_t*)&t;
}

__device__ __forceinline__ float gelu_f(float x)
{
    float x3 = x * x * x;
    return 0.5f * x * (1.0f + tanhf(0.7978845608028654f * (x + 0.044715f * x3)));
}

__device__ __forceinline__ void cpa16(uint32_t s, const void* g) {
    asm volatile("cp.async.ca.shared.global [%0], [%1], 16;" :: "r"(s), "l"(g));
}
#define CPA_COMMIT() asm volatile("cp.async.commit_group;" ::: "memory")
#define CPA_WAIT1()  asm volatile("cp.async.wait_group 1;" ::: "memory")
#define CPA_WAIT0()  asm volatile("cp.async.wait_group 0;" ::: "memory")

__device__ __forceinline__ void ldm4(uint32_t* r, uint32_t addr) {
    asm volatile("ldmatrix.sync.aligned.m8n8.x4.shared.b16 {%0,%1,%2,%3}, [%4];"
        : "=r"(r[0]), "=r"(r[1]), "=r"(r[2]), "=r"(r[3]) : "r"(addr));
}

__device__ __forceinline__ void mma16816(float* d, const uint32_t* a, const uint32_t* b) {
    asm volatile("mma.sync.aligned.m16n8k16.row.col.f32.bf16.bf16.f32 "
        "{%0,%1,%2,%3}, {%4,%5,%6,%7}, {%8,%9}, {%0,%1,%2,%3};"
        : "+f"(d[0]), "+f"(d[1]), "+f"(d[2]), "+f"(d[3])
        : "r"(a[0]), "r"(a[1]), "r"(a[2]), "r"(a[3]), "r"(b[0]), "r"(b[1]));
}

// ---------------------------------------------------------------------------
// Scratch (static __device__)
// ---------------------------------------------------------------------------
__device__ __align__(128) __nv_bfloat16 g_lnh  [M_ * C_],   g_lnl  [M_ * C_];
__device__ __align__(128) __nv_bfloat16 g_atth [M_ * C_],   g_attl [M_ * C_];
__device__ __align__(128) __nv_bfloat16 g_fch  [M_ * FC_],  g_fcl  [M_ * FC_];
__device__ __align__(128) __nv_bfloat16 g_qkvh [M_ * C3_],  g_qkvl [M_ * C3_];
__device__ __align__(128) __nv_bfloat16 g_wqkvh[C3_ * C_],  g_wqkvl[C3_ * C_];
__device__ __align__(128) __nv_bfloat16 g_woh  [C_ * C_],   g_wol  [C_ * C_];
__device__ __align__(128) __nv_bfloat16 g_wfh  [FC_ * C_],  g_wfl  [FC_ * C_];
__device__ __align__(128) __nv_bfloat16 g_wph  [C_ * FC_],  g_wpl  [C_ * FC_];
__device__ __align__(128) float g_bqkv[C3_];
__device__ __align__(128) float g_x1[M_ * C_];

// ---------------------------------------------------------------------------
// Weight transpose + bf16 split: W[K][N] -> Th[N][K], Tl[N][K]
// ---------------------------------------------------------------------------
__global__ void wsplitT_kernel(const float* __restrict__ W,
                               __nv_bfloat16* __restrict__ Th,
                               __nv_bfloat16* __restrict__ Tl,
                               int K, int N)
{
    __shared__ float ts[32][33];
    int tx = threadIdx.x & 31, ty = threadIdx.x >> 5;
    int bx = blockIdx.x, by = blockIdx.y;
    #pragma unroll
    for (int i = 0; i < 4; i++) {
        int k = by * 32 + ty + i * 8;
        ts[ty + i * 8][tx] = W[(size_t)k * N + bx * 32 + tx];
    }
    __syncthreads();
    #pragma unroll
    for (int i = 0; i < 4; i++) {
        int n = bx * 32 + ty + i * 8;
        int k = by * 32 + tx;
        float v = ts[tx][ty + i * 8];
        __nv_bfloat16 h, l; split_bf16(v, h, l);
        Th[(size_t)n * K + k] = h;
        Tl[(size_t)n * K + k] = l;
    }
}

// concat 3 bias vectors of length C_ into one [3C]
__global__ void bias3_kernel(const float* __restrict__ a, const float* __restrict__ b,
                             const float* __restrict__ c, float* __restrict__ o)
{
    int i = blockIdx.x * 256 + threadIdx.x;
    if (i < C_) { o[i] = a[i]; o[C_ + i] = b[i]; o[2 * C_ + i] = c[i]; }
}

// ---------------------------------------------------------------------------
// LayerNorm -> bf16 hi/lo
// ---------------------------------------------------------------------------
__global__ void ln_kernel(const float* __restrict__ x,
                          const float* __restrict__ gamma,
                          const float* __restrict__ beta,
                          __nv_bfloat16* __restrict__ yh,
                          __nv_bfloat16* __restrict__ yl)
{
    int row = blockIdx.x;
    int t   = threadIdx.x;
    const float4* xr = (const float4*)(x + (size_t)row * C_);
    float4 xv = xr[t];

    float s  = xv.x + xv.y + xv.z + xv.w;
    float ss = fmaf(xv.x, xv.x, fmaf(xv.y, xv.y, fmaf(xv.z, xv.z, xv.w * xv.w)));
    #pragma unroll
    for (int o = 16; o > 0; o >>= 1) {
        s  += __shfl_xor_sync(0xffffffffu, s,  o);
        ss += __shfl_xor_sync(0xffffffffu, ss, o);
    }
    __shared__ float rs[8], rss[8];
    __shared__ float s_mu, s_inv;
    int w = t >> 5, lane = t & 31;
    if (lane == 0) { rs[w] = s; rss[w] = ss; }
    __syncthreads();
    if (t == 0) {
        float ts = 0.f, tss = 0.f;
        #pragma unroll
        for (int i = 0; i < 8; i++) { ts += rs[i]; tss += rss[i]; }
        float mu  = ts * (1.0f / (float)C_);
        float var = tss * (1.0f / (float)C_) - mu * mu;
        s_mu = mu;  s_inv = rsqrtf(var + 1e-5f);
    }
    __syncthreads();
    float mu = s_mu, inv = s_inv;

    float4 gv = ((const float4*)gamma)[t];
    float4 bv = ((const float4*)beta)[t];
    float o[4];
    o[0] = (xv.x - mu) * inv * gv.x + bv.x;
    o[1] = (xv.y - mu) * inv * gv.y + bv.y;
    o[2] = (xv.z - mu) * inv * gv.z + bv.z;
    o[3] = (xv.w - mu) * inv * gv.w + bv.w;

    union { __nv_bfloat16 b[4]; uint2 u; } ph, pl;
    #pragma unroll
    for (int i = 0; i < 4; i++) split_bf16(o[i], ph.b[i], pl.b[i]);
    ((uint2*)(yh + (size_t)row * C_))[t] = ph.u;
    ((uint2*)(yl + (size_t)row * C_))[t] = pl.u;
}

// ---------------------------------------------------------------------------
// Tensor-core GEMM via mma.sync (split-bf16 x3, fp32 accum)
// CTA tile 128x256, BK=32, 8 warps (2M x 4N), warp tile 64x64.
//   epi 0: out fp32 = acc + bias
//   epi 1: outH/outL bf16 = split(gelu(acc + bias))
//   epi 2: out fp32 = acc + bias + resid
//   epi 3: outH/outL bf16 = split(acc + bias)
// ---------------------------------------------------------------------------
#define A_TILE_B (128 * 80)              // 10240
#define B_TILE_B (256 * 80)              // 20480
#define STAGE_B  (2 * A_TILE_B + 2 * B_TILE_B)   // 61440
#define GEMM_SMEM (2 * STAGE_B)          // 122880
#define oAh 0
#define oAl A_TILE_B
#define oBh (2 * A_TILE_B)
#define oBl (2 * A_TILE_B + B_TILE_B)

__global__ void __launch_bounds__(256, 1)
gemm_tc(const __nv_bfloat16* __restrict__ Ah, const __nv_bfloat16* __restrict__ Al,
        const __nv_bfloat16* __restrict__ Bh, const __nv_bfloat16* __restrict__ Bl,
        const float* __restrict__ bias, const float* __restrict__ resid,
        float* __restrict__ Cout,
        __nv_bfloat16* __restrict__ outH, __nv_bfloat16* __restrict__ outL,
        int Nn, int Kk, int epi)
{
    extern __shared__ __align__(128) char smem[];
    const uint32_t sb = smem_u32(smem);

    const int tid  = threadIdx.x;
    const int wid  = tid >> 5;
    const int lane = tid & 31;
    const int bx = blockIdx.x;      // N tile (256)
    const int by = blockIdx.y;      // M tile (128)
    const int wm = wid >> 2;        // 0..1  rows wm*64..+63
    const int wn = wid & 3;         // 0..3  cols wn*64..+63

    const char* gAh = (const char*)(Ah + (size_t)(by * 128) * Kk);
    const char* gAl = (const char*)(Al + (size_t)(by * 128) * Kk);
    const char* gBh = (const char*)(Bh + (size_t)(bx * 256) * Kk);
    const char* gBl = (const char*)(Bl + (size_t)(bx * 256) * Kk);
    const size_t rowBytes = (size_t)Kk * 2;

    // fragment address components
    const uint32_t aRowOff = (uint32_t)((wm * 64 + (lane & 15)) * 80 + (lane >> 4) * 16);
    const uint32_t bRowOff = (uint32_t)((wn * 64 + (lane & 7) + ((lane >> 4) << 3)) * 80
                                        + ((lane >> 3) & 1) * 16);

    float acc[4][8][4];
    #pragma unroll
    for (int mt = 0; mt < 4; mt++)
        #pragma unroll
        for (int nt = 0; nt < 8; nt++)
            #pragma unroll
            for (int e = 0; e < 4; e++) acc[mt][nt][e] = 0.f;

    const int nch = Kk >> 5;

    // prefetch chunk 0
    {
        const uint32_t sbb = sb;
        #pragma unroll
        for (int i = 0; i < 2; i++) {
            int s = tid + i * 256;             // A segs 0..511
            int r = s >> 2, c = (s & 3) * 16;
            cpa16(sbb + oAh + r * 80 + c, gAh + (size_t)r * rowBytes + c);
            cpa16(sbb + oAl + r * 80 + c, gAl + (size_t)r * rowBytes + c);
        }
        #pragma unroll
        for (int i = 0; i < 4; i++) {
            int s = tid + i * 256;             // B segs 0..1023
            int r = s >> 2, c = (s & 3) * 16;
            cpa16(sbb + oBh + r * 80 + c, gBh + (size_t)r * rowBytes + c);
            cpa16(sbb + oBl + r * 80 + c, gBl + (size_t)r * rowBytes + c);
        }
        CPA_COMMIT();
    }

    for (int ch = 0; ch < nch; ch++) {
        if (ch + 1 < nch) {
            const uint32_t sbb = sb + ((ch + 1) & 1) * STAGE_B;
            const size_t kb = (size_t)(ch + 1) * 64;
            #pragma unroll
            for (int i = 0; i < 2; i++) {
                int s = tid + i * 256;
                int r = s >> 2, c = (s & 3) * 16;
                cpa16(sbb + oAh + r * 80 + c, gAh + (size_t)r * rowBytes + kb + c);
                cpa16(sbb + oAl + r * 80 + c, gAl + (size_t)r * rowBytes + kb + c);
            }
            #pragma unroll
            for (int i = 0; i < 4; i++) {
                int s = tid + i * 256;
                int r = s >> 2, c = (s & 3) * 16;
                cpa16(sbb + oBh + r * 80 + c, gBh + (size_t)r * rowBytes + kb + c);
                cpa16(sbb + oBl + r * 80 + c, gBl + (size_t)r * rowBytes + kb + c);
            }
            CPA_COMMIT();
            CPA_WAIT1();
        } else {
            CPA_WAIT0();
        }
        __syncthreads();

        const uint32_t buf = sb + (ch & 1) * STAGE_B;
        const uint32_t aHi = buf + oAh + aRowOff;
        const uint32_t aLo = buf + oAl + aRowOff;
        const uint32_t bHi = buf + oBh + bRowOff;
        const uint32_t bLo = buf + oBl + bRowOff;

        #pragma unroll
        for (int k16 = 0; k16 < 2; k16++) {
            const uint32_t ko = (uint32_t)(k16 * 32);
            uint32_t ahf[4][4], alf[4][4];
            #pragma unroll
            for (int mt = 0; mt < 4; mt++) {
                ldm4(ahf[mt], aHi + (uint32_t)(mt * 16 * 80) + ko);
                ldm4(alf[mt], aLo + (uint32_t)(mt * 16 * 80) + ko);
            }
            #pragma unroll
            for (int p = 0; p < 4; p++) {
                uint32_t rh[4], rl[4];
                ldm4(rh, bHi + (uint32_t)(p * 16 * 80) + ko);
                ldm4(rl, bLo + (uint32_t)(p * 16 * 80) + ko);
                const int nt0 = 2 * p, nt1 = 2 * p + 1;
                #pragma unroll
                for (int mt = 0; mt < 4; mt++) {
                    mma16816(acc[mt][nt0], ahf[mt], rh);
                    mma16816(acc[mt][nt0], ahf[mt], rl);
                    mma16816(acc[mt][nt0], alf[mt], rh);
                    mma16816(acc[mt][nt1], ahf[mt], rh + 2);
                    mma16816(acc[mt][nt1], ahf[mt], rl + 2);
                    mma16816(acc[mt][nt1], alf[mt], rh + 2);
                }
            }
        }
        __syncthreads();
    }

    // epilogue
    const int rowBase = by * 128 + wm * 64 + (lane >> 2);
    const int colBase = bx * 256 + wn * 64 + (lane & 3) * 2;
    #pragma unroll
    for (int mt = 0; mt < 4; mt++) {
        #pragma unroll
        for (int nt = 0; nt < 8; nt++) {
            const int col = colBase + nt * 8;
            const float b0 = bias[col], b1 = bias[col + 1];
            const int ra = rowBase + mt * 16;
            const int rb = ra + 8;
            float v00 = acc[mt][nt][0] + b0, v01 = acc[mt][nt][1] + b1;
            float v10 = acc[mt][nt][2] + b0, v11 = acc[mt][nt][3] + b1;
            if (epi == 1 || epi == 3) {
                if (epi == 1) {
                    v00 = gelu_f(v00); v01 = gelu_f(v01);
                    v10 = gelu_f(v10); v11 = gelu_f(v11);
                }
                *(uint32_t*)&outH[(size_t)ra * Nn + col] = pack_split_hi(v00, v01);
                *(uint32_t*)&outL[(size_t)ra * Nn + col] = pack_split_lo(v00, v01);
                *(uint32_t*)&outH[(size_t)rb * Nn + col] = pack_split_hi(v10, v11);
                *(uint32_t*)&outL[(size_t)rb * Nn + col] = pack_split_lo(v10, v11);
            } else {
                if (epi == 2) {
                    const float2 r0v = *(const float2*)&resid[(size_t)ra * Nn + col];
                    const float2 r1v = *(const float2*)&resid[(size_t)rb * Nn + col];
                    v00 += r0v.x; v01 += r0v.y; v10 += r1v.x; v11 += r1v.y;
                }
                *(float2*)&Cout[(size_t)ra * Nn + col] = make_float2(v00, v01);
                *(float2*)&Cout[(size_t)rb * Nn + col] = make_float2(v10, v11);
            }
        }
    }
}

// ---------------------------------------------------------------------------
// Tensor-core flash attention (split-bf16 x3, causal).
// Q/K/V read from fused [M][qkvStride] layout (pointers pre-offset per tensor).
// ---------------------------------------------------------------------------
#define STR_ 72
#define SQ_BYTES (128 * STR_ * 2)
#define SK_BYTES (64 * STR_ * 2)
#define ATTN_SMEM (2 * SQ_BYTES + 4 * SK_BYTES)   // 73728

__global__ void __launch_bounds__(256, 1)
attn_tc(const __nv_bfloat16* __restrict__ Qh_, const __nv_bfloat16* __restrict__ Ql_,
        const __nv_bfloat16* __restrict__ Kh_, const __nv_bfloat16* __restrict__ Kl_,
        const __nv_bfloat16* __restrict__ Vh_, const __nv_bfloat16* __restrict__ Vl_,
        __nv_bfloat16* __restrict__ Oh_, __nv_bfloat16* __restrict__ Ol_,
        int qkvStride)
{
    extern __shared__ __align__(128) char smem[];
    const uint32_t sQh = smem_u32(smem);
    const uint32_t sQl = sQh + SQ_BYTES;
    const uint32_t sKh = sQl + SQ_BYTES;
    const uint32_t sKl = sKh + SK_BYTES;
    const uint32_t sVh = sKl + SK_BYTES;
    const uint32_t sVl = sVh + SK_BYTES;
    __nv_bfloat16* mVh = (__nv_bfloat16*)(smem + 2 * SQ_BYTES + 2 * SK_BYTES);
    __nv_bfloat16* mVl = (__nv_bfloat16*)(smem + 2 * SQ_BYTES + 3 * SK_BYTES);

    const int qt = blockIdx.x, h = blockIdx.y, b = blockIdx.z;
    const int tid = threadIdx.x, wid = tid >> 5, lane = tid & 31;
    const int wm = wid;

    const size_t rowB = (size_t)qkvStride * 2;
    const size_t qbase = ((size_t)(b * T_ + qt * 128)) * rowB + (size_t)h * 128;

    #pragma unroll
    for (int i = 0; i < 4; i++) {
        int c = tid + i * 256;
        int r = c >> 3, ch = (c & 7) * 16;
        cpa16(sQh + r * 144 + ch, (const char*)Qh_ + qbase + (size_t)r * rowB + ch);
        cpa16(sQl + r * 144 + ch, (const char*)Ql_ + qbase + (size_t)r * rowB + ch);
    }
    CPA_COMMIT();

    const uint32_t aOff  = (uint32_t)((wm * 16 + (lane & 15)) * 144 + (lane >> 4) * 16);
    const uint32_t bRow  = (uint32_t)((lane & 7) + ((lane >> 4) << 3));
    const uint32_t bByte = (uint32_t)(((lane >> 3) & 1) * 16);

    uint32_t qh[4][4], ql[4][4];
    float oacc[8][4];
    #pragma unroll
    for (int nd = 0; nd < 8; nd++)
        #pragma unroll
        for (int e = 0; e < 4; e++) oacc[nd][e] = 0.f;
    float m0 = -1e30f, m1 = -1e30f, l0 = 0.f, l1 = 0.f;

    const int qr0 = qt * 128 + wm * 16 + (lane >> 2);
    const int nkt = 2 * qt + 2;

    for (int kt = 0; kt < nkt; kt++) {
        __syncthreads();
        const size_t kbase = ((size_t)(b * T_ + kt * 64)) * rowB + (size_t)h * 128;
        #pragma unroll
        for (int i = 0; i < 2; i++) {
            int c = tid + i * 256;
            int r = c >> 3, ch = (c & 7) * 16;
            cpa16(sKh + r * 144 + ch, (const char*)Kh_ + kbase + (size_t)r * rowB + ch);
            cpa16(sKl + r * 144 + ch, (const char*)Kl_ + kbase + (size_t)r * rowB + ch);
        }
        CPA_COMMIT();

        uint4 vregH[2], vregL[2];
        int vkey[2], vd0[2];
        #pragma unroll
        for (int i = 0; i < 2; i++) {
            int c = tid + i * 256;
            vkey[i] = c & 63;
            vd0[i]  = (c >> 6) * 8;
            vregH[i] = *(const uint4*)((const char*)Vh_ + kbase + (size_t)vkey[i] * rowB + (c >> 6) * 16);
            vregL[i] = *(const uint4*)((const char*)Vl_ + kbase + (size_t)vkey[i] * rowB + (c >> 6) * 16);
        }

        CPA_WAIT0();

        #pragma unroll
        for (int i = 0; i < 2; i++) {
            const __nv_bfloat16* eh = (const __nv_bfloat16*)&vregH[i];
            const __nv_bfloat16* el = (const __nv_bfloat16*)&vregL[i];
            #pragma unroll
            for (int j = 0; j < 8; j++) {
                mVh[(vd0[i] + j) * STR_ + vkey[i]] = eh[j];
                mVl[(vd0[i] + j) * STR_ + vkey[i]] = el[j];
            }
        }
        __syncthreads();

        if (kt == 0) {
            #pragma unroll
            for (int ks = 0; ks < 4; ks++) {
                ldm4(qh[ks], sQh + aOff + ks * 32);
                ldm4(ql[ks], sQl + aOff + ks * 32);
            }
        }

        // S = Q.K^T
        float sa[8][4];
        #pragma unroll
        for (int nt = 0; nt < 8; nt++)
            #pragma unroll
            for (int e = 0; e < 4; e++) sa[nt][e] = 0.f;

        #pragma unroll
        for (int ks = 0; ks < 4; ks++) {
            uint32_t bh[8][2], bl[8][2];
            #pragma unroll
            for (int p = 0; p < 4; p++) {
                uint32_t rh[4], rl[4];
                ldm4(rh, sKh + (p * 16 + bRow) * 144 + bByte + ks * 32);
                ldm4(rl, sKl + (p * 16 + bRow) * 144 + bByte + ks * 32);
                bh[2 * p][0] = rh[0]; bh[2 * p][1] = rh[1];
                bh[2 * p + 1][0] = rh[2]; bh[2 * p + 1][1] = rh[3];
                bl[2 * p][0] = rl[0]; bl[2 * p][1] = rl[1];
                bl[2 * p + 1][0] = rl[2]; bl[2 * p + 1][1] = rl[3];
            }
            #pragma unroll
            for (int nt = 0; nt < 8; nt++) {
                mma16816(sa[nt], qh[ks], bh[nt]);
                mma16816(sa[nt], qh[ks], bl[nt]);
                mma16816(sa[nt], ql[ks], bh[nt]);
            }
        }

        // online softmax
        float tm0 = -1e30f, tm1 = -1e30f;
        #pragma unroll
        for (int nt = 0; nt < 8; nt++) {
            #pragma unroll
            for (int j = 0; j < 2; j++) {
                int kcol = kt * 64 + nt * 8 + (lane & 3) * 2 + j;
                float s0 = sa[nt][j] * 0.125f;
                float s1 = sa[nt][2 + j] * 0.125f;
                if (kcol > qr0)     s0 = -1e30f;
                if (kcol > qr0 + 8) s1 = -1e30f;
                sa[nt][j] = s0;  sa[nt][2 + j] = s1;
                tm0 = fmaxf(tm0, s0);  tm1 = fmaxf(tm1, s1);
            }
        }
        tm0 = fmaxf(tm0, __shfl_xor_sync(0xffffffffu, tm0, 1));
        tm0 = fmaxf(tm0, __shfl_xor_sync(0xffffffffu, tm0, 2));
        tm1 = fmaxf(tm1, __shfl_xor_sync(0xffffffffu, tm1, 1));
        tm1 = fmaxf(tm1, __shfl_xor_sync(0xffffffffu, tm1, 2));

        const float nm0 = fmaxf(m0, tm0), nm1 = fmaxf(m1, tm1);
        const float cr0 = __expf(m0 - nm0), cr1 = __expf(m1 - nm1);
        m0 = nm0; m1 = nm1;

        float rs0 = 0.f, rs1 = 0.f;
        #pragma unroll
        for (int nt = 0; nt < 8; nt++) {
            #pragma unroll
            for (int j = 0; j < 2; j++) {
                float p0 = __expf(sa[nt][j] - m0);
                float p1 = __expf(sa[nt][2 + j] - m1);
                sa[nt][j] = p0;  sa[nt][2 + j] = p1;
                rs0 += p0;  rs1 += p1;
            }
        }
        rs0 += __shfl_xor_sync(0xffffffffu, rs0, 1);
        rs0 += __shfl_xor_sync(0xffffffffu, rs0, 2);
        rs1 += __shfl_xor_sync(0xffffffffu, rs1, 1);
        rs1 += __shfl_xor_sync(0xffffffffu, rs1, 2);
        l0 = l0 * cr0 + rs0;
        l1 = l1 * cr1 + rs1;

        #pragma unroll
        for (int nd = 0; nd < 8; nd++) {
            oacc[nd][0] *= cr0; oacc[nd][1] *= cr0;
            oacc[nd][2] *= cr1; oacc[nd][3] *= cr1;
        }

        uint32_t pH[4][4], pL[4][4];
        #pragma unroll
        for (int ks = 0; ks < 4; ks++) {
            const int t0 = 2 * ks, t1 = 2 * ks + 1;
            pH[ks][0] = pack_split_hi(sa[t0][0], sa[t0][1]);
            pL[ks][0] = pack_split_lo(sa[t0][0], sa[t0][1]);
            pH[ks][1] = pack_split_hi(sa[t0][2], sa[t0][3]);
            pL[ks][1] = pack_split_lo(sa[t0][2], sa[t0][3]);
            pH[ks][2] = pack_split_hi(sa[t1][0], sa[t1][1]);
            pL[ks][2] = pack_split_lo(sa[t1][0], sa[t1][1]);
            pH[ks][3] = pack_split_hi(sa[t1][2], sa[t1][3]);
            pL[ks][3] = pack_split_lo(sa[t1][2], sa[t1][3]);
        }

        #pragma unroll
        for (int ks = 0; ks < 4; ks++) {
            uint32_t vh[8][2], vl[8][2];
            #pragma unroll
            for (int p = 0; p < 4; p++) {
                uint32_t rh[4], rl[4];
                ldm4(rh, sVh + (p * 16 + bRow) * 144 + bByte + ks * 32);
                ldm4(rl, sVl + (p * 16 + bRow) * 144 + bByte + ks * 32);
                vh[2 * p][0] = rh[0]; vh[2 * p][1] = rh[1];
                vh[2 * p + 1][0] = rh[2]; vh[2 * p + 1][1] = rh[3];
                vl[2 * p][0] = rl[0]; vl[2 * p][1] = rl[1];
                vl[2 * p + 1][0] = rl[2]; vl[2 * p + 1][1] = rl[3];
            }
            #pragma unroll
            for (int nd = 0; nd < 8; nd++) {
                mma16816(oacc[nd], pH[ks], vh[nd]);
                mma16816(oacc[nd], pH[ks], vl[nd]);
                mma16816(oacc[nd], pL[ks], vh[nd]);
            }
        }
    }

    const float il0 = 1.0f / l0, il1 = 1.0f / l1;
    const size_t tok0 = (size_t)(b * T_ + qt * 128 + wm * 16 + (lane >> 2));
    const int colb = h * 64 + (lane & 3) * 2;
    #pragma unroll
    for (int nd = 0; nd < 8; nd++) {
        const int col = colb + nd * 8;
        float v00 = oacc[nd][0] * il0, v01 = oacc[nd][1] * il0;
        float v10 = oacc[nd][2] * il1, v11 = oacc[nd][3] * il1;
        *(uint32_t*)&Oh_[tok0 * C_ + col]       = pack_split_hi(v00, v01);
        *(uint32_t*)&Ol_[tok0 * C_ + col]       = pack_split_lo(v00, v01);
        *(uint32_t*)&Oh_[(tok0 + 8) * C_ + col] = pack_split_hi(v10, v11);
        *(uint32_t*)&Ol_[(tok0 + 8) * C_ + col] = pack_split_lo(v10, v11);
    }
}

// ---------------------------------------------------------------------------
// Launch
// ---------------------------------------------------------------------------
extern "C" void kernel_launch(void* const* d_in, const int* in_sizes, int n_in,
                              void* d_out, int out_size)
{
    const float* x      = (const float*)d_in[0];
    const float* Wq     = (const float*)d_in[1];
    const float* bq     = (const float*)d_in[2];
    const float* Wk     = (const float*)d_in[3];
    const float* bk     = (const float*)d_in[4];
    const float* Wv     = (const float*)d_in[5];
    const float* bv     = (const float*)d_in[6];
    const float* Wo     = (const float*)d_in[7];
    const float* bo     = (const float*)d_in[8];
    const float* ln1_g  = (const float*)d_in[9];
    const float* ln1_b  = (const float*)d_in[10];
    const float* ln2_g  = (const float*)d_in[11];
    const float* ln2_b  = (const float*)d_in[12];
    const float* W_fc   = (const float*)d_in[13];
    const float* b_fc   = (const float*)d_in[14];
    const float* W_proj = (const float*)d_in[15];
    const float* b_proj = (const float*)d_in[16];
    float* out = (float*)d_out;

    __nv_bfloat16 *lnh, *lnl, *atth, *attl, *fch, *fcl, *qkvh, *qkvl;
    __nv_bfloat16 *wqkvh, *wqkvl, *woh, *wol, *wfh, *wfl, *wph, *wpl;
    float *x1, *bqkv;
    cudaGetSymbolAddress((void**)&lnh,   g_lnh);   cudaGetSymbolAddress((void**)&lnl,   g_lnl);
    cudaGetSymbolAddress((void**)&atth,  g_atth);  cudaGetSymbolAddress((void**)&attl,  g_attl);
    cudaGetSymbolAddress((void**)&fch,   g_fch);   cudaGetSymbolAddress((void**)&fcl,   g_fcl);
    cudaGetSymbolAddress((void**)&qkvh,  g_qkvh);  cudaGetSymbolAddress((void**)&qkvl,  g_qkvl);
    cudaGetSymbolAddress((void**)&wqkvh, g_wqkvh); cudaGetSymbolAddress((void**)&wqkvl, g_wqkvl);
    cudaGetSymbolAddress((void**)&woh,   g_woh);   cudaGetSymbolAddress((void**)&wol,   g_wol);
    cudaGetSymbolAddress((void**)&wfh,   g_wfh);   cudaGetSymbolAddress((void**)&wfl,   g_wfl);
    cudaGetSymbolAddress((void**)&wph,   g_wph);   cudaGetSymbolAddress((void**)&wpl,   g_wpl);
    cudaGetSymbolAddress((void**)&x1,    g_x1);
    cudaGetSymbolAddress((void**)&bqkv,  g_bqkv);

    cudaFuncSetAttribute(attn_tc, cudaFuncAttributeMaxDynamicSharedMemorySize, ATTN_SMEM);
    cudaFuncSetAttribute(gemm_tc, cudaFuncAttributeMaxDynamicSharedMemorySize, GEMM_SMEM);

    dim3 wtb(256);
    // fused QKV weight: rows 0..C-1 = Q, C..2C-1 = K, 2C..3C-1 = V
    wsplitT_kernel<<<dim3(C_/32,  C_/32),  wtb>>>(Wq, wqkvh,             wqkvl,             C_, C_);
    wsplitT_kernel<<<dim3(C_/32,  C_/32),  wtb>>>(Wk, wqkvh + C_ * C_,   wqkvl + C_ * C_,   C_, C_);
    wsplitT_kernel<<<dim3(C_/32,  C_/32),  wtb>>>(Wv, wqkvh + 2*C_*C_,   wqkvl + 2*C_*C_,   C_, C_);
    wsplitT_kernel<<<dim3(C_/32,  C_/32),  wtb>>>(Wo,     woh, wol, C_,  C_);
    wsplitT_kernel<<<dim3(FC_/32, C_/32),  wtb>>>(W_fc,   wfh, wfl, C_,  FC_);
    wsplitT_kernel<<<dim3(C_/32,  FC_/32), wtb>>>(W_proj, wph, wpl, FC_, C_);
    bias3_kernel<<<C_/256, 256>>>(bq, bk, bv, bqkv);

    dim3 gQKV(C3_ / 256, M_ / 128);   // (12, 64)
    dim3 gC  (C_  / 256, M_ / 128);   // (4, 64)
    dim3 gF  (FC_ / 256, M_ / 128);   // (16, 64)

    // 1) ln1
    ln_kernel<<<M_, 256>>>(x, ln1_g, ln1_b, lnh, lnl);
    // 2) fused QKV -> bf16 hi/lo [M][3C]
    gemm_tc<<<gQKV, 256, GEMM_SMEM>>>(lnh, lnl, wqkvh, wqkvl, bqkv, nullptr,
                                      nullptr, qkvh, qkvl, C3_, C_, 3);
    // 3) tensor-core attention (fused-layout Q/K/V)
    attn_tc<<<dim3(T_ / 128, H_, B_), 256, ATTN_SMEM>>>(
        qkvh, qkvl, qkvh + C_, qkvl + C_, qkvh + 2 * C_, qkvl + 2 * C_,
        atth, attl, C3_);
    // 4) x1 = x + att @ Wo + bo
    gemm_tc<<<gC, 256, GEMM_SMEM>>>(atth, attl, woh, wol, bo, x, x1,
                                    nullptr, nullptr, C_, C_, 2);
    // 5) ln2
    ln_kernel<<<M_, 256>>>(x1, ln2_g, ln2_b, lnh, lnl);
    // 6) fc = gelu(ln2 @ W_fc + b_fc) -> bf16 hi/lo
    gemm_tc<<<gF, 256, GEMM_SMEM>>>(lnh, lnl, wfh, wfl, b_fc, nullptr,
                                    nullptr, fch, fcl, FC_, C_, 1);
    // 7) out = x1 + fc @ W_proj + b_proj
    gemm_tc<<<gC, 256, GEMM_SMEM>>>(fch, fcl, wph, wpl, b_proj, x1, out,
                                    nullptr, nullptr, C_, FC_, 2);
}